// round 10
// baseline (speedup 1.0000x reference)
#include <cuda_runtime.h>
#include <cuda_fp16.h>
#include <stdint.h>
#include <math.h>

#define HW    4096
#define NPIX  131072
#define NCH   128
#define NT    2048           // 64-pixel tiles
#define NCTA  148

__device__ __half g_xh[(size_t)NCH * NPIX];     // x as fp16
__device__ __half g_fh[(size_t)NCH * NPIX];     // fmax as fp16
__device__ __half g_yh[(size_t)256 * NPIX];     // Y as fp16 (all 256 ch)
__device__ __half g_yl[(size_t)128 * NPIX];     // Y residual, ch 0..127 (x_proc path)
__device__ float g_H[(size_t)128 * NPIX];
__device__ float g_Wfold[128 * 256];
__device__ float g_ypart[256 * 296 * 2];
__device__ float g_hpart[128 * 296 * 2];
__device__ float g_a[256];
__device__ float g_b2n[128];
__device__ float g_a3[128];
__device__ float g_d3[128];

__device__ __forceinline__ uint32_t smem_u32(const void* p) {
    uint32_t a;
    asm("{ .reg .u64 t; cvta.to.shared.u64 t, %1; cvt.u32.u64 %0, t; }" : "=r"(a) : "l"(p));
    return a;
}
#define LDSM4(r, addr) \
    asm volatile("ldmatrix.sync.aligned.m8n8.x4.shared.b16 {%0,%1,%2,%3}, [%4];" \
        : "=r"((r)[0]), "=r"((r)[1]), "=r"((r)[2]), "=r"((r)[3]) : "r"(addr))
#define LDSM4T(r, addr) \
    asm volatile("ldmatrix.sync.aligned.m8n8.x4.trans.shared.b16 {%0,%1,%2,%3}, [%4];" \
        : "=r"((r)[0]), "=r"((r)[1]), "=r"((r)[2]), "=r"((r)[3]) : "r"(addr))
#define MMA(c, a, b0v, b1v) \
    asm volatile("mma.sync.aligned.m16n8k16.row.col.f32.f16.f16.f32 " \
        "{%0,%1,%2,%3},{%4,%5,%6,%7},{%8,%9},{%0,%1,%2,%3};" \
        : "+f"((c)[0]), "+f"((c)[1]), "+f"((c)[2]), "+f"((c)[3]) \
        : "r"((a)[0]), "r"((a)[1]), "r"((a)[2]), "r"((a)[3]), "r"(b0v), "r"(b1v))
#define CPA16(s, g) asm volatile("cp.async.cg.shared.global [%0], [%1], 16;" :: "r"(s), "l"(g))
#define CPC()       asm volatile("cp.async.commit_group;" ::: "memory")
#define CPW2()      asm volatile("cp.async.wait_group 2;" ::: "memory")

__device__ __forceinline__ float gelu(float v) { return 0.5f * v * (1.0f + erff(v * 0.70710678f)); }
__device__ __forceinline__ void hsplit(float v, __half& h, __half& l) {
    h = __float2half_rn(v); l = __float2half_rn(v - __half2float(h));
}

// ---- K1: fmax; write x and fmax as fp16 ----
__global__ void k_fmax(const float* __restrict__ x) {
    __shared__ float sm[4096];
    size_t o = (size_t)blockIdx.x * HW;
    for (int i = threadIdx.x; i < 4096; i += 256) sm[i] = x[o + i];
    __syncthreads();
    for (int i = threadIdx.x; i < 4096; i += 256) {
        int h = i >> 6, w = i & 63;
        float v = sm[i], m = v;
        #pragma unroll
        for (int s = 2; s <= 32; s <<= 1) {
            m = fminf(m, sm[(h << 6) | ((w + s) & 63)]);
            m = fminf(m, sm[(h << 6) | ((w - s) & 63)]);
            m = fminf(m, sm[(((h + s) & 63) << 6) | w]);
            m = fminf(m, sm[(((h - s) & 63) << 6) | w]);
        }
        g_xh[o + i] = __float2half_rn(v);
        g_fh[o + i] = __float2half_rn(v - m);
    }
}

// ============ GEMM-Y: Y[128ch][64px] = Wh[128x128] * Xh, single pass =========
// SMEM: Ah[128][136] @0 (34816 B), B triple buf [128][72] @34816 + b*18432.
#define Y_AS   136
#define Y_BS   72
#define Y_B0   34816u
#define Y_BSZ  18432u
#define SM_Y   90112

__global__ __launch_bounds__(256, 2) void k_gemmY(const float* __restrict__ w_in,
                                                  const float* __restrict__ w_diff) {
    extern __shared__ __align__(16) char smem[];
    const uint32_t sb = smem_u32(smem);
    const int tid = threadIdx.x;
    const int lane = tid & 31, wid = tid >> 5;
    const int wr = wid >> 1, wc = wid & 1;          // 4x2 warp grid
    const int cta = blockIdx.x, ot = blockIdx.y;
    const float* W = ot ? w_diff : w_in;
    const __half* S = ot ? g_fh : g_xh;

    for (int idx = tid; idx < 128 * 128; idx += 256) {
        int m = idx >> 7, k = idx & 127;
        *(__half*)(smem + (m * Y_AS + k) * 2) = __float2half_rn(W[idx]);
    }
    __syncthreads();

    const int la = lane & 15, lb = lane >> 4;
    const int mb = wr * 32, nb = wc * 32;
    const uint32_t aBase = sb + (uint32_t)((mb + la) * Y_AS * 2 + lb * 16);
    const uint32_t bBase = sb + Y_B0 + (uint32_t)(la * Y_BS * 2 + (nb + lb * 8) * 2);

    float st1[4] = {0.f, 0.f, 0.f, 0.f}, st2[4] = {0.f, 0.f, 0.f, 0.f};
    int buf = 0;

    // prefetch 2 tiles
    #pragma unroll
    for (int pf = 0; pf < 2; pf++) {
        int tt = cta + pf * NCTA;
        if (tt < NT) {
            int p0 = tt * 64;
            size_t base = (size_t)(p0 >> 12) * 128 * HW + (p0 & 4095);
            uint32_t bo = Y_B0 + (uint32_t)pf * Y_BSZ;
            #pragma unroll
            for (int rq = 0; rq < 4; rq++) {
                int q = tid + rq * 256;
                int k = q >> 3, c8 = q & 7;
                CPA16(sb + bo + (uint32_t)(k * Y_BS * 2 + c8 * 16),
                      S + base + (size_t)k * HW + c8 * 8);
            }
        }
        CPC();
    }

    int nb3 = 2;  // next buffer slot to fill (mod 3)
    for (int t = cta; t < NT; t += NCTA) {
        int tn = t + 2 * NCTA;
        if (tn < NT) {
            int p0n = tn * 64;
            size_t base = (size_t)(p0n >> 12) * 128 * HW + (p0n & 4095);
            uint32_t bo = Y_B0 + (uint32_t)nb3 * Y_BSZ;
            #pragma unroll
            for (int rq = 0; rq < 4; rq++) {
                int q = tid + rq * 256;
                int k = q >> 3, c8 = q & 7;
                CPA16(sb + bo + (uint32_t)(k * Y_BS * 2 + c8 * 16),
                      S + base + (size_t)k * HW + c8 * 8);
            }
        }
        CPC(); CPW2();
        __syncthreads();

        float c[2][4][4];
        #pragma unroll
        for (int i = 0; i < 2; i++)
            #pragma unroll
            for (int j = 0; j < 4; j++)
                #pragma unroll
                for (int q = 0; q < 4; q++) c[i][j][q] = 0.f;

        uint32_t bA = bBase + (uint32_t)buf * Y_BSZ;
        #pragma unroll
        for (int ks = 0; ks < 8; ks++) {
            uint32_t a0[4], a1[4], b0[4], b1[4];
            LDSM4(a0, aBase + ks * 32);
            LDSM4(a1, aBase + ks * 32 + 16 * Y_AS * 2);
            LDSM4T(b0, bA + ks * (16 * Y_BS * 2));
            LDSM4T(b1, bA + ks * (16 * Y_BS * 2) + 32);
            MMA(c[0][0], a0, b0[0], b0[1]);
            MMA(c[0][1], a0, b0[2], b0[3]);
            MMA(c[0][2], a0, b1[0], b1[1]);
            MMA(c[0][3], a0, b1[2], b1[3]);
            MMA(c[1][0], a1, b0[0], b0[1]);
            MMA(c[1][1], a1, b0[2], b0[3]);
            MMA(c[1][2], a1, b1[0], b1[1]);
            MMA(c[1][3], a1, b1[2], b1[3]);
        }
        __syncthreads();    // all reads of buf done before it is refilled

        int p0 = t * 64;
        int r = lane >> 2, cq = (lane & 3) * 2;
        #pragma unroll
        for (int i = 0; i < 2; i++) {
            int chA = ot * 128 + mb + i * 16 + r;
            size_t gA = (size_t)chA * NPIX + p0;
            size_t gB = gA + (size_t)8 * NPIX;
            #pragma unroll
            for (int j = 0; j < 4; j++) {
                int n = nb + j * 8 + cq;
                float v0 = c[i][j][0], v1 = c[i][j][1], v2 = c[i][j][2], v3 = c[i][j][3];
                st1[i * 2]     += v0 + v1; st2[i * 2]     += v0 * v0 + v1 * v1;
                st1[i * 2 + 1] += v2 + v3; st2[i * 2 + 1] += v2 * v2 + v3 * v3;
                __half h0, l0, h1, l1;
                hsplit(v0, h0, l0); hsplit(v1, h1, l1);
                __half2 hh; hh.x = h0; hh.y = h1;
                *(__half2*)(g_yh + gA + n) = hh;
                if (ot == 0) { __half2 ll; ll.x = l0; ll.y = l1; *(__half2*)(g_yl + gA + n) = ll; }
                hsplit(v2, h0, l0); hsplit(v3, h1, l1);
                hh.x = h0; hh.y = h1;
                *(__half2*)(g_yh + gB + n) = hh;
                if (ot == 0) { __half2 ll; ll.x = l0; ll.y = l1; *(__half2*)(g_yl + gB + n) = ll; }
            }
        }
        buf = (buf == 2) ? 0 : buf + 1;
        nb3 = (nb3 == 2) ? 0 : nb3 + 1;
    }

    #pragma unroll
    for (int s = 0; s < 4; s++) {
        #pragma unroll
        for (int d = 1; d < 4; d <<= 1) {
            st1[s] += __shfl_xor_sync(0xffffffffu, st1[s], d);
            st2[s] += __shfl_xor_sync(0xffffffffu, st2[s], d);
        }
    }
    if ((lane & 3) == 0) {
        int r = lane >> 2;
        int col = cta * 2 + wc;
        #pragma unroll
        for (int s = 0; s < 4; s++) {
            int ch = ot * 128 + wr * 32 + (s >> 1) * 16 + r + (s & 1) * 8;
            g_ypart[((size_t)ch * 296 + col) * 2 + 0] = st1[s];
            g_ypart[((size_t)ch * 296 + col) * 2 + 1] = st2[s];
        }
    }
}

// ---- reduce Y stats -> a[256], b2n[128] ----
__global__ void k_reduceY(const float* __restrict__ g_ibn, const float* __restrict__ be_ibn,
                          const float* __restrict__ gbn) {
    int c = blockIdx.x, t = threadIdx.x;
    double s = 0.0, ss = 0.0;
    for (int i = t; i < 296; i += 128) {
        s  += (double)g_ypart[((size_t)c * 296 + i) * 2 + 0];
        ss += (double)g_ypart[((size_t)c * 296 + i) * 2 + 1];
    }
    __shared__ double sh[128], shh[128];
    sh[t] = s; shh[t] = ss; __syncthreads();
    for (int o = 64; o; o >>= 1) {
        if (t < o) { sh[t] += sh[t + o]; shh[t] += shh[t + o]; }
        __syncthreads();
    }
    if (t == 0) {
        double mu = sh[0] / (double)NPIX;
        double var = shh[0] / (double)NPIX - mu * mu;
        float g = (c < 128) ? g_ibn[c] : gbn[c - 128];
        float a = g / sqrtf((float)var + 1e-5f);
        g_a[c] = a;
        if (c < 128) g_b2n[c] = be_ibn[c] - a * (float)mu;
    }
}

__global__ void k_wfold(const float* __restrict__ w_mr) {
    int i = blockIdx.x * 256 + threadIdx.x;
    g_Wfold[i] = w_mr[i] * g_a[i & 255];
}

// ============ GEMM-H: H[128][64px] = Wfh[128x256] * Yh, single pass ==========
// Ah[128][264] @0 (67584 B), B triple buf [256][72] @67584 + b*36864.
#define H_AS   264
#define H_BS   72
#define H_B0   67584u
#define H_BSZ  36864u
#define SM_H   178176

__global__ __launch_bounds__(256, 1) void k_gemmH() {
    extern __shared__ __align__(16) char smem[];
    const uint32_t sb = smem_u32(smem);
    const int tid = threadIdx.x;
    const int lane = tid & 31, wid = tid >> 5;
    const int wr = wid >> 1, wc = wid & 1;
    const int cta = blockIdx.x;

    for (int idx = tid; idx < 128 * 256; idx += 256) {
        int m = idx >> 8, k = idx & 255;
        *(__half*)(smem + (m * H_AS + k) * 2) = __float2half_rn(g_Wfold[idx]);
    }
    __syncthreads();

    const int la = lane & 15, lb = lane >> 4;
    const int mb = wr * 32, nb = wc * 32;
    const uint32_t aBase = sb + (uint32_t)((mb + la) * H_AS * 2 + lb * 16);
    const uint32_t bBase = sb + H_B0 + (uint32_t)(la * H_BS * 2 + (nb + lb * 8) * 2);

    float st1[4] = {0.f, 0.f, 0.f, 0.f}, st2[4] = {0.f, 0.f, 0.f, 0.f};
    int buf = 0;

    #pragma unroll
    for (int pf = 0; pf < 2; pf++) {
        int tt = cta + pf * NCTA;
        if (tt < NT) {
            int p0 = tt * 64;
            uint32_t bo = H_B0 + (uint32_t)pf * H_BSZ;
            #pragma unroll
            for (int rq = 0; rq < 8; rq++) {
                int q = tid + rq * 256;
                int k = q >> 3, c8 = q & 7;
                CPA16(sb + bo + (uint32_t)(k * H_BS * 2 + c8 * 16),
                      g_yh + (size_t)k * NPIX + p0 + c8 * 8);
            }
        }
        CPC();
    }

    int nb3 = 2;
    for (int t = cta; t < NT; t += NCTA) {
        int tn = t + 2 * NCTA;
        if (tn < NT) {
            int p0n = tn * 64;
            uint32_t bo = H_B0 + (uint32_t)nb3 * H_BSZ;
            #pragma unroll
            for (int rq = 0; rq < 8; rq++) {
                int q = tid + rq * 256;
                int k = q >> 3, c8 = q & 7;
                CPA16(sb + bo + (uint32_t)(k * H_BS * 2 + c8 * 16),
                      g_yh + (size_t)k * NPIX + p0n + c8 * 8);
            }
        }
        CPC(); CPW2();
        __syncthreads();

        float c[2][4][4];
        #pragma unroll
        for (int i = 0; i < 2; i++)
            #pragma unroll
            for (int j = 0; j < 4; j++)
                #pragma unroll
                for (int q = 0; q < 4; q++) c[i][j][q] = 0.f;

        uint32_t bA = bBase + (uint32_t)buf * H_BSZ;
        #pragma unroll
        for (int ks = 0; ks < 16; ks++) {
            uint32_t a0[4], a1[4], b0[4], b1[4];
            LDSM4(a0, aBase + ks * 32);
            LDSM4(a1, aBase + ks * 32 + 16 * H_AS * 2);
            LDSM4T(b0, bA + ks * (16 * H_BS * 2));
            LDSM4T(b1, bA + ks * (16 * H_BS * 2) + 32);
            MMA(c[0][0], a0, b0[0], b0[1]);
            MMA(c[0][1], a0, b0[2], b0[3]);
            MMA(c[0][2], a0, b1[0], b1[1]);
            MMA(c[0][3], a0, b1[2], b1[3]);
            MMA(c[1][0], a1, b0[0], b0[1]);
            MMA(c[1][1], a1, b0[2], b0[3]);
            MMA(c[1][2], a1, b1[0], b1[1]);
            MMA(c[1][3], a1, b1[2], b1[3]);
        }
        __syncthreads();

        int p0 = t * 64;
        int r = lane >> 2, cq = (lane & 3) * 2;
        #pragma unroll
        for (int i = 0; i < 2; i++) {
            int chA = mb + i * 16 + r;
            float* gA = g_H + (size_t)chA * NPIX + p0;
            float* gB = gA + (size_t)8 * NPIX;
            #pragma unroll
            for (int j = 0; j < 4; j++) {
                int n = nb + j * 8 + cq;
                float v0 = c[i][j][0], v1 = c[i][j][1], v2 = c[i][j][2], v3 = c[i][j][3];
                st1[i * 2]     += v0 + v1; st2[i * 2]     += v0 * v0 + v1 * v1;
                st1[i * 2 + 1] += v2 + v3; st2[i * 2 + 1] += v2 * v2 + v3 * v3;
                float2 f0; f0.x = v0; f0.y = v1;
                float2 f1; f1.x = v2; f1.y = v3;
                *(float2*)(gA + n) = f0;
                *(float2*)(gB + n) = f1;
            }
        }
        buf = (buf == 2) ? 0 : buf + 1;
        nb3 = (nb3 == 2) ? 0 : nb3 + 1;
    }

    #pragma unroll
    for (int s = 0; s < 4; s++) {
        #pragma unroll
        for (int d = 1; d < 4; d <<= 1) {
            st1[s] += __shfl_xor_sync(0xffffffffu, st1[s], d);
            st2[s] += __shfl_xor_sync(0xffffffffu, st2[s], d);
        }
    }
    if ((lane & 3) == 0) {
        int r = lane >> 2;
        int col = cta * 2 + wc;
        #pragma unroll
        for (int s = 0; s < 4; s++) {
            int ch = wr * 32 + (s >> 1) * 16 + r + (s & 1) * 8;
            g_hpart[((size_t)ch * 296 + col) * 2 + 0] = st1[s];
            g_hpart[((size_t)ch * 296 + col) * 2 + 1] = st2[s];
        }
    }
}

// ---- reduce H stats -> a3, d3 ----
__global__ void k_reduceH(const float* __restrict__ g_mbn, const float* __restrict__ be_mbn) {
    int c = blockIdx.x, t = threadIdx.x;
    double s = 0.0, ss = 0.0;
    for (int i = t; i < 296; i += 128) {
        s  += (double)g_hpart[((size_t)c * 296 + i) * 2 + 0];
        ss += (double)g_hpart[((size_t)c * 296 + i) * 2 + 1];
    }
    __shared__ double sh[128], shh[128];
    sh[t] = s; shh[t] = ss; __syncthreads();
    for (int o = 64; o; o >>= 1) {
        if (t < o) { sh[t] += sh[t + o]; shh[t] += shh[t + o]; }
        __syncthreads();
    }
    if (t == 0) {
        double mu = sh[0] / (double)NPIX;
        double var = shh[0] / (double)NPIX - mu * mu;
        float a = g_mbn[c] / sqrtf((float)var + 1e-5f);
        g_a3[c] = a;
        g_d3[c] = be_mbn[c] - a * (float)mu;
    }
}

// ---- out = a2*(yh+yl) + b2n + gelu(a3*H + d3) ----
__global__ void k_out(float* __restrict__ out) {
    size_t i = ((size_t)blockIdx.x * 256 + threadIdx.x) * 4;
    int c = (int)((i >> 12) & 127);
    size_t b = i >> 19;
    size_t p = b * HW + (i & 4095);
    float4 h = *(const float4*)(g_H + (size_t)c * NPIX + p);
    __half2 yh0 = *(const __half2*)(g_yh + (size_t)c * NPIX + p);
    __half2 yh1 = *(const __half2*)(g_yh + (size_t)c * NPIX + p + 2);
    __half2 yl0 = *(const __half2*)(g_yl + (size_t)c * NPIX + p);
    __half2 yl1 = *(const __half2*)(g_yl + (size_t)c * NPIX + p + 2);
    float a2 = g_a[c], bn = g_b2n[c], a3 = g_a3[c], d3 = g_d3[c];
    float4 o;
    o.x = fmaf(a2, __half2float(yh0.x) + __half2float(yl0.x), bn) + gelu(fmaf(a3, h.x, d3));
    o.y = fmaf(a2, __half2float(yh0.y) + __half2float(yl0.y), bn) + gelu(fmaf(a3, h.y, d3));
    o.z = fmaf(a2, __half2float(yh1.x) + __half2float(yl1.x), bn) + gelu(fmaf(a3, h.z, d3));
    o.w = fmaf(a2, __half2float(yh1.y) + __half2float(yl1.y), bn) + gelu(fmaf(a3, h.w, d3));
    *(float4*)(out + i) = o;
}

extern "C" void kernel_launch(void* const* d_in, const int* in_sizes, int n_in,
                              void* d_out, int out_size) {
    const float* x      = (const float*)d_in[0];
    const float* w_diff = (const float*)d_in[1];
    const float* gbn    = (const float*)d_in[3];
    const float* w_in   = (const float*)d_in[5];
    const float* g_ibn  = (const float*)d_in[7];
    const float* be_ibn = (const float*)d_in[8];
    const float* w_mr   = (const float*)d_in[9];
    const float* g_mbn  = (const float*)d_in[11];
    const float* be_mbn = (const float*)d_in[12];
    float* out = (float*)d_out;

    cudaFuncSetAttribute(k_gemmY, cudaFuncAttributeMaxDynamicSharedMemorySize, SM_Y);
    cudaFuncSetAttribute(k_gemmH, cudaFuncAttributeMaxDynamicSharedMemorySize, SM_H);

    k_fmax<<<4096, 256>>>(x);
    k_gemmY<<<dim3(NCTA, 2), 256, SM_Y>>>(w_in, w_diff);
    k_reduceY<<<256, 128>>>(g_ibn, be_ibn, gbn);
    k_wfold<<<128, 256>>>(w_mr);
    k_gemmH<<<NCTA, 256, SM_H>>>();
    k_reduceH<<<128, 128>>>(g_mbn, be_mbn);
    k_out<<<16384, 256>>>(out);
}

// round 13
// speedup vs baseline: 1.4174x; 1.4174x over previous
#include <cuda_runtime.h>
#include <cuda_fp16.h>
#include <stdint.h>
#include <math.h>

#define HW    4096
#define NPIX  131072
#define NCH   128
#define NT    2048           // 64-pixel tiles
#define NCTA  148

__device__ __half g_xh[(size_t)NCH * NPIX];     // x as fp16
__device__ __half g_fh[(size_t)NCH * NPIX];     // fmax as fp16
__device__ __half g_yh[(size_t)256 * NPIX];     // Y as fp16 (all 256 ch)
__device__ __half g_yl[(size_t)128 * NPIX];     // Y residual, ch 0..127 (x_proc path)
__device__ float g_H[(size_t)128 * NPIX];
__device__ float g_Wfold[128 * 256];
__device__ float g_ypart[256 * 296 * 2];
__device__ float g_hpart[128 * 296 * 2];
__device__ float g_a[256];
__device__ float g_b2n[128];
__device__ float g_a3[128];
__device__ float g_d3[128];

__device__ __forceinline__ uint32_t smem_u32(const void* p) {
    uint32_t a;
    asm("{ .reg .u64 t; cvta.to.shared.u64 t, %1; cvt.u32.u64 %0, t; }" : "=r"(a) : "l"(p));
    return a;
}
#define LDSM4(r, addr) \
    asm volatile("ldmatrix.sync.aligned.m8n8.x4.shared.b16 {%0,%1,%2,%3}, [%4];" \
        : "=r"((r)[0]), "=r"((r)[1]), "=r"((r)[2]), "=r"((r)[3]) : "r"(addr))
#define LDSM4T(r, addr) \
    asm volatile("ldmatrix.sync.aligned.m8n8.x4.trans.shared.b16 {%0,%1,%2,%3}, [%4];" \
        : "=r"((r)[0]), "=r"((r)[1]), "=r"((r)[2]), "=r"((r)[3]) : "r"(addr))
#define MMA(c, a, b0v, b1v) \
    asm volatile("mma.sync.aligned.m16n8k16.row.col.f32.f16.f16.f32 " \
        "{%0,%1,%2,%3},{%4,%5,%6,%7},{%8,%9},{%0,%1,%2,%3};" \
        : "+f"((c)[0]), "+f"((c)[1]), "+f"((c)[2]), "+f"((c)[3]) \
        : "r"((a)[0]), "r"((a)[1]), "r"((a)[2]), "r"((a)[3]), "r"(b0v), "r"(b1v))
#define CPA16(s, g) asm volatile("cp.async.cg.shared.global [%0], [%1], 16;" :: "r"(s), "l"(g))
#define CPC()       asm volatile("cp.async.commit_group;" ::: "memory")
#define CPW1()      asm volatile("cp.async.wait_group 1;" ::: "memory")

__device__ __forceinline__ float gelu(float v) { return 0.5f * v * (1.0f + erff(v * 0.70710678f)); }
__device__ __forceinline__ void hsplit(float v, __half& h, __half& l) {
    h = __float2half_rn(v); l = __float2half_rn(v - __half2float(h));
}

// ---- K1: fmax; write x and fmax as fp16 ----
__global__ void k_fmax(const float* __restrict__ x) {
    __shared__ float sm[4096];
    size_t o = (size_t)blockIdx.x * HW;
    for (int i = threadIdx.x; i < 4096; i += 256) sm[i] = x[o + i];
    __syncthreads();
    for (int i = threadIdx.x; i < 4096; i += 256) {
        int h = i >> 6, w = i & 63;
        float v = sm[i], m = v;
        #pragma unroll
        for (int s = 2; s <= 32; s <<= 1) {
            m = fminf(m, sm[(h << 6) | ((w + s) & 63)]);
            m = fminf(m, sm[(h << 6) | ((w - s) & 63)]);
            m = fminf(m, sm[(((h + s) & 63) << 6) | w]);
            m = fminf(m, sm[(((h - s) & 63) << 6) | w]);
        }
        g_xh[o + i] = __float2half_rn(v);
        g_fh[o + i] = __float2half_rn(v - m);
    }
}

// ============ GEMM-Y: Y[128ch][64px] = Wh[128x128] * Xh, single pass =========
// SMEM: Ah[128][136] @0 (34816 B), B double buf [128][72] @34816 + b*18432.
#define Y_AS   136
#define Y_BS   72
#define Y_B0   34816u
#define Y_BSZ  18432u
#define SM_Y   71680

__global__ __launch_bounds__(256, 2) void k_gemmY(const float* __restrict__ w_in,
                                                  const float* __restrict__ w_diff) {
    extern __shared__ __align__(16) char smem[];
    const uint32_t sb = smem_u32(smem);
    const int tid = threadIdx.x;
    const int lane = tid & 31, wid = tid >> 5;
    const int wr = wid >> 1, wc = wid & 1;          // 4x2 warp grid
    const int cta = blockIdx.x, ot = blockIdx.y;
    const float* W = ot ? w_diff : w_in;
    const __half* S = ot ? g_fh : g_xh;

    for (int idx = tid; idx < 128 * 128; idx += 256) {
        int m = idx >> 7, k = idx & 127;
        *(__half*)(smem + (m * Y_AS + k) * 2) = __float2half_rn(W[idx]);
    }
    __syncthreads();

    const int la = lane & 15, lb = lane >> 4;
    const int mb = wr * 32, nb = wc * 32;
    const uint32_t aBase = sb + (uint32_t)((mb + la) * Y_AS * 2 + lb * 16);
    const uint32_t bBase = sb + Y_B0 + (uint32_t)(la * Y_BS * 2 + (nb + lb * 8) * 2);

    float st1[4] = {0.f, 0.f, 0.f, 0.f}, st2[4] = {0.f, 0.f, 0.f, 0.f};
    int buf = 0;

    {   // prefetch first tile -> buf0
        int p0 = cta * 64;
        size_t base = (size_t)(p0 >> 12) * 128 * HW + (p0 & 4095);
        #pragma unroll
        for (int rq = 0; rq < 4; rq++) {
            int q = tid + rq * 256;
            int k = q >> 3, c8 = q & 7;
            CPA16(sb + Y_B0 + (uint32_t)(k * Y_BS * 2 + c8 * 16),
                  S + base + (size_t)k * HW + c8 * 8);
        }
        CPC();
    }

    for (int t = cta; t < NT; t += NCTA) {
        int tn = t + NCTA;
        if (tn < NT) {
            int p0n = tn * 64;
            size_t base = (size_t)(p0n >> 12) * 128 * HW + (p0n & 4095);
            uint32_t bo = Y_B0 + (uint32_t)(buf ^ 1) * Y_BSZ;
            #pragma unroll
            for (int rq = 0; rq < 4; rq++) {
                int q = tid + rq * 256;
                int k = q >> 3, c8 = q & 7;
                CPA16(sb + bo + (uint32_t)(k * Y_BS * 2 + c8 * 16),
                      S + base + (size_t)k * HW + c8 * 8);
            }
        }
        CPC(); CPW1();
        __syncthreads();

        float c[2][4][4];
        #pragma unroll
        for (int i = 0; i < 2; i++)
            #pragma unroll
            for (int j = 0; j < 4; j++)
                #pragma unroll
                for (int q = 0; q < 4; q++) c[i][j][q] = 0.f;

        uint32_t bA = bBase + (uint32_t)buf * Y_BSZ;
        #pragma unroll
        for (int ks = 0; ks < 8; ks++) {
            uint32_t a0[4], a1[4], b0[4], b1[4];
            LDSM4(a0, aBase + ks * 32);
            LDSM4(a1, aBase + ks * 32 + 16 * Y_AS * 2);
            LDSM4T(b0, bA + ks * (16 * Y_BS * 2));
            LDSM4T(b1, bA + ks * (16 * Y_BS * 2) + 32);
            MMA(c[0][0], a0, b0[0], b0[1]);
            MMA(c[0][1], a0, b0[2], b0[3]);
            MMA(c[0][2], a0, b1[0], b1[1]);
            MMA(c[0][3], a0, b1[2], b1[3]);
            MMA(c[1][0], a1, b0[0], b0[1]);
            MMA(c[1][1], a1, b0[2], b0[3]);
            MMA(c[1][2], a1, b1[0], b1[1]);
            MMA(c[1][3], a1, b1[2], b1[3]);
        }
        __syncthreads();    // all reads of buf done before refill next iter

        int p0 = t * 64;
        int r = lane >> 2, cq = (lane & 3) * 2;
        #pragma unroll
        for (int i = 0; i < 2; i++) {
            int chA = ot * 128 + mb + i * 16 + r;
            size_t gA = (size_t)chA * NPIX + p0;
            size_t gB = gA + (size_t)8 * NPIX;
            #pragma unroll
            for (int j = 0; j < 4; j++) {
                int n = nb + j * 8 + cq;
                float v0 = c[i][j][0], v1 = c[i][j][1], v2 = c[i][j][2], v3 = c[i][j][3];
                st1[i * 2]     += v0 + v1; st2[i * 2]     += v0 * v0 + v1 * v1;
                st1[i * 2 + 1] += v2 + v3; st2[i * 2 + 1] += v2 * v2 + v3 * v3;
                __half h0, l0, h1, l1;
                hsplit(v0, h0, l0); hsplit(v1, h1, l1);
                __half2 hh; hh.x = h0; hh.y = h1;
                *(__half2*)(g_yh + gA + n) = hh;
                if (ot == 0) { __half2 ll; ll.x = l0; ll.y = l1; *(__half2*)(g_yl + gA + n) = ll; }
                hsplit(v2, h0, l0); hsplit(v3, h1, l1);
                hh.x = h0; hh.y = h1;
                *(__half2*)(g_yh + gB + n) = hh;
                if (ot == 0) { __half2 ll; ll.x = l0; ll.y = l1; *(__half2*)(g_yl + gB + n) = ll; }
            }
        }
        buf ^= 1;
    }

    #pragma unroll
    for (int s = 0; s < 4; s++) {
        #pragma unroll
        for (int d = 1; d < 4; d <<= 1) {
            st1[s] += __shfl_xor_sync(0xffffffffu, st1[s], d);
            st2[s] += __shfl_xor_sync(0xffffffffu, st2[s], d);
        }
    }
    if ((lane & 3) == 0) {
        int r = lane >> 2;
        int col = cta * 2 + wc;
        #pragma unroll
        for (int s = 0; s < 4; s++) {
            int ch = ot * 128 + wr * 32 + (s >> 1) * 16 + r + (s & 1) * 8;
            g_ypart[((size_t)ch * 296 + col) * 2 + 0] = st1[s];
            g_ypart[((size_t)ch * 296 + col) * 2 + 1] = st2[s];
        }
    }
}

// ---- reduce Y stats -> a[256], b2n[128] ----
__global__ void k_reduceY(const float* __restrict__ g_ibn, const float* __restrict__ be_ibn,
                          const float* __restrict__ gbn) {
    int c = blockIdx.x, t = threadIdx.x;
    double s = 0.0, ss = 0.0;
    for (int i = t; i < 296; i += 128) {
        s  += (double)g_ypart[((size_t)c * 296 + i) * 2 + 0];
        ss += (double)g_ypart[((size_t)c * 296 + i) * 2 + 1];
    }
    __shared__ double sh[128], shh[128];
    sh[t] = s; shh[t] = ss; __syncthreads();
    for (int o = 64; o; o >>= 1) {
        if (t < o) { sh[t] += sh[t + o]; shh[t] += shh[t + o]; }
        __syncthreads();
    }
    if (t == 0) {
        double mu = sh[0] / (double)NPIX;
        double var = shh[0] / (double)NPIX - mu * mu;
        float g = (c < 128) ? g_ibn[c] : gbn[c - 128];
        float a = g / sqrtf((float)var + 1e-5f);
        g_a[c] = a;
        if (c < 128) g_b2n[c] = be_ibn[c] - a * (float)mu;
    }
}

__global__ void k_wfold(const float* __restrict__ w_mr) {
    int i = blockIdx.x * 256 + threadIdx.x;
    g_Wfold[i] = w_mr[i] * g_a[i & 255];
}

// ============ GEMM-H: H[128][64px] = Wfh[128x256] * Yh, single pass ==========
// Ah[128][264] @0 (67584 B), B double buf [256][72] @67584 + b*36864.
#define H_AS   264
#define H_BS   72
#define H_B0   67584u
#define H_BSZ  36864u
#define SM_H   141312

__global__ __launch_bounds__(256, 1) void k_gemmH() {
    extern __shared__ __align__(16) char smem[];
    const uint32_t sb = smem_u32(smem);
    const int tid = threadIdx.x;
    const int lane = tid & 31, wid = tid >> 5;
    const int wr = wid >> 1, wc = wid & 1;
    const int cta = blockIdx.x;

    for (int idx = tid; idx < 128 * 256; idx += 256) {
        int m = idx >> 8, k = idx & 255;
        *(__half*)(smem + (m * H_AS + k) * 2) = __float2half_rn(g_Wfold[idx]);
    }
    __syncthreads();

    const int la = lane & 15, lb = lane >> 4;
    const int mb = wr * 32, nb = wc * 32;
    const uint32_t aBase = sb + (uint32_t)((mb + la) * H_AS * 2 + lb * 16);
    const uint32_t bBase = sb + H_B0 + (uint32_t)(la * H_BS * 2 + (nb + lb * 8) * 2);

    float st1[4] = {0.f, 0.f, 0.f, 0.f}, st2[4] = {0.f, 0.f, 0.f, 0.f};
    int buf = 0;

    {
        int p0 = cta * 64;
        #pragma unroll
        for (int rq = 0; rq < 8; rq++) {
            int q = tid + rq * 256;
            int k = q >> 3, c8 = q & 7;
            CPA16(sb + H_B0 + (uint32_t)(k * H_BS * 2 + c8 * 16),
                  g_yh + (size_t)k * NPIX + p0 + c8 * 8);
        }
        CPC();
    }

    for (int t = cta; t < NT; t += NCTA) {
        int tn = t + NCTA;
        if (tn < NT) {
            int p0n = tn * 64;
            uint32_t bo = H_B0 + (uint32_t)(buf ^ 1) * H_BSZ;
            #pragma unroll
            for (int rq = 0; rq < 8; rq++) {
                int q = tid + rq * 256;
                int k = q >> 3, c8 = q & 7;
                CPA16(sb + bo + (uint32_t)(k * H_BS * 2 + c8 * 16),
                      g_yh + (size_t)k * NPIX + p0n + c8 * 8);
            }
        }
        CPC(); CPW1();
        __syncthreads();

        float c[2][4][4];
        #pragma unroll
        for (int i = 0; i < 2; i++)
            #pragma unroll
            for (int j = 0; j < 4; j++)
                #pragma unroll
                for (int q = 0; q < 4; q++) c[i][j][q] = 0.f;

        uint32_t bA = bBase + (uint32_t)buf * H_BSZ;
        #pragma unroll
        for (int ks = 0; ks < 16; ks++) {
            uint32_t a0[4], a1[4], b0[4], b1[4];
            LDSM4(a0, aBase + ks * 32);
            LDSM4(a1, aBase + ks * 32 + 16 * H_AS * 2);
            LDSM4T(b0, bA + ks * (16 * H_BS * 2));
            LDSM4T(b1, bA + ks * (16 * H_BS * 2) + 32);
            MMA(c[0][0], a0, b0[0], b0[1]);
            MMA(c[0][1], a0, b0[2], b0[3]);
            MMA(c[0][2], a0, b1[0], b1[1]);
            MMA(c[0][3], a0, b1[2], b1[3]);
            MMA(c[1][0], a1, b0[0], b0[1]);
            MMA(c[1][1], a1, b0[2], b0[3]);
            MMA(c[1][2], a1, b1[0], b1[1]);
            MMA(c[1][3], a1, b1[2], b1[3]);
        }
        __syncthreads();

        int p0 = t * 64;
        int r = lane >> 2, cq = (lane & 3) * 2;
        #pragma unroll
        for (int i = 0; i < 2; i++) {
            int chA = mb + i * 16 + r;
            float* gA = g_H + (size_t)chA * NPIX + p0;
            float* gB = gA + (size_t)8 * NPIX;
            #pragma unroll
            for (int j = 0; j < 4; j++) {
                int n = nb + j * 8 + cq;
                float v0 = c[i][j][0], v1 = c[i][j][1], v2 = c[i][j][2], v3 = c[i][j][3];
                st1[i * 2]     += v0 + v1; st2[i * 2]     += v0 * v0 + v1 * v1;
                st1[i * 2 + 1] += v2 + v3; st2[i * 2 + 1] += v2 * v2 + v3 * v3;
                float2 f0; f0.x = v0; f0.y = v1;
                float2 f1; f1.x = v2; f1.y = v3;
                *(float2*)(gA + n) = f0;
                *(float2*)(gB + n) = f1;
            }
        }
        buf ^= 1;
    }

    #pragma unroll
    for (int s = 0; s < 4; s++) {
        #pragma unroll
        for (int d = 1; d < 4; d <<= 1) {
            st1[s] += __shfl_xor_sync(0xffffffffu, st1[s], d);
            st2[s] += __shfl_xor_sync(0xffffffffu, st2[s], d);
        }
    }
    if ((lane & 3) == 0) {
        int r = lane >> 2;
        int col = cta * 2 + wc;
        #pragma unroll
        for (int s = 0; s < 4; s++) {
            int ch = wr * 32 + (s >> 1) * 16 + r + (s & 1) * 8;
            g_hpart[((size_t)ch * 296 + col) * 2 + 0] = st1[s];
            g_hpart[((size_t)ch * 296 + col) * 2 + 1] = st2[s];
        }
    }
}

// ---- reduce H stats -> a3, d3 ----
__global__ void k_reduceH(const float* __restrict__ g_mbn, const float* __restrict__ be_mbn) {
    int c = blockIdx.x, t = threadIdx.x;
    double s = 0.0, ss = 0.0;
    for (int i = t; i < 296; i += 128) {
        s  += (double)g_hpart[((size_t)c * 296 + i) * 2 + 0];
        ss += (double)g_hpart[((size_t)c * 296 + i) * 2 + 1];
    }
    __shared__ double sh[128], shh[128];
    sh[t] = s; shh[t] = ss; __syncthreads();
    for (int o = 64; o; o >>= 1) {
        if (t < o) { sh[t] += sh[t + o]; shh[t] += shh[t + o]; }
        __syncthreads();
    }
    if (t == 0) {
        double mu = sh[0] / (double)NPIX;
        double var = shh[0] / (double)NPIX - mu * mu;
        float a = g_mbn[c] / sqrtf((float)var + 1e-5f);
        g_a3[c] = a;
        g_d3[c] = be_mbn[c] - a * (float)mu;
    }
}

// ---- out = a2*(yh+yl) + b2n + gelu(a3*H + d3) ----
__global__ void k_out(float* __restrict__ out) {
    size_t i = ((size_t)blockIdx.x * 256 + threadIdx.x) * 4;
    int c = (int)((i >> 12) & 127);
    size_t b = i >> 19;
    size_t p = b * HW + (i & 4095);
    float4 h = *(const float4*)(g_H + (size_t)c * NPIX + p);
    __half2 yh0 = *(const __half2*)(g_yh + (size_t)c * NPIX + p);
    __half2 yh1 = *(const __half2*)(g_yh + (size_t)c * NPIX + p + 2);
    __half2 yl0 = *(const __half2*)(g_yl + (size_t)c * NPIX + p);
    __half2 yl1 = *(const __half2*)(g_yl + (size_t)c * NPIX + p + 2);
    float a2 = g_a[c], bn = g_b2n[c], a3 = g_a3[c], d3 = g_d3[c];
    float4 o;
    o.x = fmaf(a2, __half2float(yh0.x) + __half2float(yl0.x), bn) + gelu(fmaf(a3, h.x, d3));
    o.y = fmaf(a2, __half2float(yh0.y) + __half2float(yl0.y), bn) + gelu(fmaf(a3, h.y, d3));
    o.z = fmaf(a2, __half2float(yh1.x) + __half2float(yl1.x), bn) + gelu(fmaf(a3, h.z, d3));
    o.w = fmaf(a2, __half2float(yh1.y) + __half2float(yl1.y), bn) + gelu(fmaf(a3, h.w, d3));
    *(float4*)(out + i) = o;
}

extern "C" void kernel_launch(void* const* d_in, const int* in_sizes, int n_in,
                              void* d_out, int out_size) {
    const float* x      = (const float*)d_in[0];
    const float* w_diff = (const float*)d_in[1];
    const float* gbn    = (const float*)d_in[3];
    const float* w_in   = (const float*)d_in[5];
    const float* g_ibn  = (const float*)d_in[7];
    const float* be_ibn = (const float*)d_in[8];
    const float* w_mr   = (const float*)d_in[9];
    const float* g_mbn  = (const float*)d_in[11];
    const float* be_mbn = (const float*)d_in[12];
    float* out = (float*)d_out;

    cudaFuncSetAttribute(k_gemmY, cudaFuncAttributeMaxDynamicSharedMemorySize, SM_Y);
    cudaFuncSetAttribute(k_gemmH, cudaFuncAttributeMaxDynamicSharedMemorySize, SM_H);

    k_fmax<<<4096, 256>>>(x);
    k_gemmY<<<dim3(NCTA, 2), 256, SM_Y>>>(w_in, w_diff);
    k_reduceY<<<256, 128>>>(g_ibn, be_ibn, gbn);
    k_wfold<<<128, 256>>>(w_mr);
    k_gemmH<<<NCTA, 256, SM_H>>>();
    k_reduceH<<<128, 128>>>(g_mbn, be_mbn);
    k_out<<<16384, 256>>>(out);
}

// round 14
// speedup vs baseline: 1.4828x; 1.0461x over previous
#include <cuda_runtime.h>
#include <cuda_fp16.h>
#include <stdint.h>
#include <math.h>

#define HW    4096
#define NPIX  131072
#define NCH   128
#define NT    2048           // 64-pixel tiles
#define NCTA  148

__device__ __half g_xh[(size_t)NCH * NPIX];     // x as fp16
__device__ __half g_fh[(size_t)NCH * NPIX];     // fmax as fp16
__device__ __half g_yh[(size_t)256 * NPIX];     // Y as fp16 (all 256 ch)
__device__ __half g_Hh[(size_t)128 * NPIX];     // H as fp16
__device__ float g_ypart[256 * 296 * 2];
__device__ float g_hpart[128 * 296 * 2];
__device__ float g_a[256];
__device__ float g_b2n[128];
__device__ float g_a3[128];
__device__ float g_d3[128];

__device__ __forceinline__ uint32_t smem_u32(const void* p) {
    uint32_t a;
    asm("{ .reg .u64 t; cvta.to.shared.u64 t, %1; cvt.u32.u64 %0, t; }" : "=r"(a) : "l"(p));
    return a;
}
#define LDSM4(r, addr) \
    asm volatile("ldmatrix.sync.aligned.m8n8.x4.shared.b16 {%0,%1,%2,%3}, [%4];" \
        : "=r"((r)[0]), "=r"((r)[1]), "=r"((r)[2]), "=r"((r)[3]) : "r"(addr))
#define LDSM4T(r, addr) \
    asm volatile("ldmatrix.sync.aligned.m8n8.x4.trans.shared.b16 {%0,%1,%2,%3}, [%4];" \
        : "=r"((r)[0]), "=r"((r)[1]), "=r"((r)[2]), "=r"((r)[3]) : "r"(addr))
#define MMA(c, a, b0v, b1v) \
    asm volatile("mma.sync.aligned.m16n8k16.row.col.f32.f16.f16.f32 " \
        "{%0,%1,%2,%3},{%4,%5,%6,%7},{%8,%9},{%0,%1,%2,%3};" \
        : "+f"((c)[0]), "+f"((c)[1]), "+f"((c)[2]), "+f"((c)[3]) \
        : "r"((a)[0]), "r"((a)[1]), "r"((a)[2]), "r"((a)[3]), "r"(b0v), "r"(b1v))
#define CPA16(s, g) asm volatile("cp.async.cg.shared.global [%0], [%1], 16;" :: "r"(s), "l"(g))
#define CPC()       asm volatile("cp.async.commit_group;" ::: "memory")
#define CPW1()      asm volatile("cp.async.wait_group 1;" ::: "memory")

__device__ __forceinline__ float gelu(float v) { return 0.5f * v * (1.0f + erff(v * 0.70710678f)); }

// ---- K1: fmax; write x and fmax as fp16 ----
__global__ void k_fmax(const float* __restrict__ x) {
    __shared__ float sm[4096];
    size_t o = (size_t)blockIdx.x * HW;
    for (int i = threadIdx.x; i < 4096; i += 256) sm[i] = x[o + i];
    __syncthreads();
    for (int i = threadIdx.x; i < 4096; i += 256) {
        int h = i >> 6, w = i & 63;
        float v = sm[i], m = v;
        #pragma unroll
        for (int s = 2; s <= 32; s <<= 1) {
            m = fminf(m, sm[(h << 6) | ((w + s) & 63)]);
            m = fminf(m, sm[(h << 6) | ((w - s) & 63)]);
            m = fminf(m, sm[(((h + s) & 63) << 6) | w]);
            m = fminf(m, sm[(((h - s) & 63) << 6) | w]);
        }
        g_xh[o + i] = __float2half_rn(v);
        g_fh[o + i] = __float2half_rn(v - m);
    }
}

// ============ GEMM-Y: Y[128ch][64px] = Wh[128x128] * Xh, single pass =========
// SMEM: Ah[128][136] @0 (34816 B), B double buf [128][72] @34816 + b*18432.
#define Y_AS   136
#define Y_BS   72
#define Y_B0   34816u
#define Y_BSZ  18432u
#define SM_Y   71680

__global__ __launch_bounds__(256, 2) void k_gemmY(const float* __restrict__ w_in,
                                                  const float* __restrict__ w_diff) {
    extern __shared__ __align__(16) char smem[];
    const uint32_t sb = smem_u32(smem);
    const int tid = threadIdx.x;
    const int lane = tid & 31, wid = tid >> 5;
    const int wr = wid >> 1, wc = wid & 1;          // 4x2 warp grid
    const int cta = blockIdx.x, ot = blockIdx.y;
    const float* W = ot ? w_diff : w_in;
    const __half* S = ot ? g_fh : g_xh;

    for (int idx = tid; idx < 128 * 128; idx += 256) {
        int m = idx >> 7, k = idx & 127;
        *(__half*)(smem + (m * Y_AS + k) * 2) = __float2half_rn(W[idx]);
    }
    __syncthreads();

    const int la = lane & 15, lb = lane >> 4;
    const int mb = wr * 32, nb = wc * 32;
    const uint32_t aBase = sb + (uint32_t)((mb + la) * Y_AS * 2 + lb * 16);
    const uint32_t bBase = sb + Y_B0 + (uint32_t)(la * Y_BS * 2 + (nb + lb * 8) * 2);

    float st1[4] = {0.f, 0.f, 0.f, 0.f}, st2[4] = {0.f, 0.f, 0.f, 0.f};
    int buf = 0;

    {   // prefetch first tile -> buf0
        int p0 = cta * 64;
        size_t base = (size_t)(p0 >> 12) * 128 * HW + (p0 & 4095);
        #pragma unroll
        for (int rq = 0; rq < 4; rq++) {
            int q = tid + rq * 256;
            int k = q >> 3, c8 = q & 7;
            CPA16(sb + Y_B0 + (uint32_t)(k * Y_BS * 2 + c8 * 16),
                  S + base + (size_t)k * HW + c8 * 8);
        }
        CPC();
    }

    for (int t = cta; t < NT; t += NCTA) {
        int tn = t + NCTA;
        if (tn < NT) {
            int p0n = tn * 64;
            size_t base = (size_t)(p0n >> 12) * 128 * HW + (p0n & 4095);
            uint32_t bo = Y_B0 + (uint32_t)(buf ^ 1) * Y_BSZ;
            #pragma unroll
            for (int rq = 0; rq < 4; rq++) {
                int q = tid + rq * 256;
                int k = q >> 3, c8 = q & 7;
                CPA16(sb + bo + (uint32_t)(k * Y_BS * 2 + c8 * 16),
                      S + base + (size_t)k * HW + c8 * 8);
            }
        }
        CPC(); CPW1();
        __syncthreads();

        float c[2][4][4];
        #pragma unroll
        for (int i = 0; i < 2; i++)
            #pragma unroll
            for (int j = 0; j < 4; j++)
                #pragma unroll
                for (int q = 0; q < 4; q++) c[i][j][q] = 0.f;

        uint32_t bA = bBase + (uint32_t)buf * Y_BSZ;
        #pragma unroll
        for (int ks = 0; ks < 8; ks++) {
            uint32_t a0[4], a1[4], b0[4], b1[4];
            LDSM4(a0, aBase + ks * 32);
            LDSM4(a1, aBase + ks * 32 + 16 * Y_AS * 2);
            LDSM4T(b0, bA + ks * (16 * Y_BS * 2));
            LDSM4T(b1, bA + ks * (16 * Y_BS * 2) + 32);
            MMA(c[0][0], a0, b0[0], b0[1]);
            MMA(c[0][1], a0, b0[2], b0[3]);
            MMA(c[0][2], a0, b1[0], b1[1]);
            MMA(c[0][3], a0, b1[2], b1[3]);
            MMA(c[1][0], a1, b0[0], b0[1]);
            MMA(c[1][1], a1, b0[2], b0[3]);
            MMA(c[1][2], a1, b1[0], b1[1]);
            MMA(c[1][3], a1, b1[2], b1[3]);
        }
        __syncthreads();    // all reads of buf done before refill next iter

        int p0 = t * 64;
        int r = lane >> 2, cq = (lane & 3) * 2;
        #pragma unroll
        for (int i = 0; i < 2; i++) {
            int chA = ot * 128 + mb + i * 16 + r;
            size_t gA = (size_t)chA * NPIX + p0;
            size_t gB = gA + (size_t)8 * NPIX;
            #pragma unroll
            for (int j = 0; j < 4; j++) {
                int n = nb + j * 8 + cq;
                float v0 = c[i][j][0], v1 = c[i][j][1], v2 = c[i][j][2], v3 = c[i][j][3];
                st1[i * 2]     += v0 + v1; st2[i * 2]     += v0 * v0 + v1 * v1;
                st1[i * 2 + 1] += v2 + v3; st2[i * 2 + 1] += v2 * v2 + v3 * v3;
                __half2 hh; hh.x = __float2half_rn(v0); hh.y = __float2half_rn(v1);
                *(__half2*)(g_yh + gA + n) = hh;
                hh.x = __float2half_rn(v2); hh.y = __float2half_rn(v3);
                *(__half2*)(g_yh + gB + n) = hh;
            }
        }
        buf ^= 1;
    }

    #pragma unroll
    for (int s = 0; s < 4; s++) {
        #pragma unroll
        for (int d = 1; d < 4; d <<= 1) {
            st1[s] += __shfl_xor_sync(0xffffffffu, st1[s], d);
            st2[s] += __shfl_xor_sync(0xffffffffu, st2[s], d);
        }
    }
    if ((lane & 3) == 0) {
        int r = lane >> 2;
        int col = cta * 2 + wc;
        #pragma unroll
        for (int s = 0; s < 4; s++) {
            int ch = ot * 128 + wr * 32 + (s >> 1) * 16 + r + (s & 1) * 8;
            g_ypart[((size_t)ch * 296 + col) * 2 + 0] = st1[s];
            g_ypart[((size_t)ch * 296 + col) * 2 + 1] = st2[s];
        }
    }
}

// ---- reduce Y stats -> a[256], b2n[128] ----
__global__ void k_reduceY(const float* __restrict__ g_ibn, const float* __restrict__ be_ibn,
                          const float* __restrict__ gbn) {
    int c = blockIdx.x, t = threadIdx.x;
    double s = 0.0, ss = 0.0;
    for (int i = t; i < 296; i += 128) {
        s  += (double)g_ypart[((size_t)c * 296 + i) * 2 + 0];
        ss += (double)g_ypart[((size_t)c * 296 + i) * 2 + 1];
    }
    __shared__ double sh[128], shh[128];
    sh[t] = s; shh[t] = ss; __syncthreads();
    for (int o = 64; o; o >>= 1) {
        if (t < o) { sh[t] += sh[t + o]; shh[t] += shh[t + o]; }
        __syncthreads();
    }
    if (t == 0) {
        double mu = sh[0] / (double)NPIX;
        double var = shh[0] / (double)NPIX - mu * mu;
        float g = (c < 128) ? g_ibn[c] : gbn[c - 128];
        float a = g / sqrtf((float)var + 1e-5f);
        g_a[c] = a;
        if (c < 128) g_b2n[c] = be_ibn[c] - a * (float)mu;
    }
}

// ============ GEMM-H: H[128][64px] = fp16(w_mr*a)[128x256] * Yh ==============
// Ah[128][264] @0 (67584 B), B double buf [256][72] @67584 + b*36864.
#define H_AS   264
#define H_BS   72
#define H_B0   67584u
#define H_BSZ  36864u
#define SM_H   141312

__global__ __launch_bounds__(256, 1) void k_gemmH(const float* __restrict__ w_mr) {
    extern __shared__ __align__(16) char smem[];
    const uint32_t sb = smem_u32(smem);
    const int tid = threadIdx.x;
    const int lane = tid & 31, wid = tid >> 5;
    const int wr = wid >> 1, wc = wid & 1;
    const int cta = blockIdx.x;

    // fold BN scale into weights inline (replaces k_wfold)
    for (int idx = tid; idx < 128 * 256; idx += 256) {
        int m = idx >> 8, k = idx & 255;
        *(__half*)(smem + (m * H_AS + k) * 2) = __float2half_rn(w_mr[idx] * g_a[k]);
    }
    __syncthreads();

    const int la = lane & 15, lb = lane >> 4;
    const int mb = wr * 32, nb = wc * 32;
    const uint32_t aBase = sb + (uint32_t)((mb + la) * H_AS * 2 + lb * 16);
    const uint32_t bBase = sb + H_B0 + (uint32_t)(la * H_BS * 2 + (nb + lb * 8) * 2);

    float st1[4] = {0.f, 0.f, 0.f, 0.f}, st2[4] = {0.f, 0.f, 0.f, 0.f};
    int buf = 0;

    {
        int p0 = cta * 64;
        #pragma unroll
        for (int rq = 0; rq < 8; rq++) {
            int q = tid + rq * 256;
            int k = q >> 3, c8 = q & 7;
            CPA16(sb + H_B0 + (uint32_t)(k * H_BS * 2 + c8 * 16),
                  g_yh + (size_t)k * NPIX + p0 + c8 * 8);
        }
        CPC();
    }

    for (int t = cta; t < NT; t += NCTA) {
        int tn = t + NCTA;
        if (tn < NT) {
            int p0n = tn * 64;
            uint32_t bo = H_B0 + (uint32_t)(buf ^ 1) * H_BSZ;
            #pragma unroll
            for (int rq = 0; rq < 8; rq++) {
                int q = tid + rq * 256;
                int k = q >> 3, c8 = q & 7;
                CPA16(sb + bo + (uint32_t)(k * H_BS * 2 + c8 * 16),
                      g_yh + (size_t)k * NPIX + p0n + c8 * 8);
            }
        }
        CPC(); CPW1();
        __syncthreads();

        float c[2][4][4];
        #pragma unroll
        for (int i = 0; i < 2; i++)
            #pragma unroll
            for (int j = 0; j < 4; j++)
                #pragma unroll
                for (int q = 0; q < 4; q++) c[i][j][q] = 0.f;

        uint32_t bA = bBase + (uint32_t)buf * H_BSZ;
        #pragma unroll
        for (int ks = 0; ks < 16; ks++) {
            uint32_t a0[4], a1[4], b0[4], b1[4];
            LDSM4(a0, aBase + ks * 32);
            LDSM4(a1, aBase + ks * 32 + 16 * H_AS * 2);
            LDSM4T(b0, bA + ks * (16 * H_BS * 2));
            LDSM4T(b1, bA + ks * (16 * H_BS * 2) + 32);
            MMA(c[0][0], a0, b0[0], b0[1]);
            MMA(c[0][1], a0, b0[2], b0[3]);
            MMA(c[0][2], a0, b1[0], b1[1]);
            MMA(c[0][3], a0, b1[2], b1[3]);
            MMA(c[1][0], a1, b0[0], b0[1]);
            MMA(c[1][1], a1, b0[2], b0[3]);
            MMA(c[1][2], a1, b1[0], b1[1]);
            MMA(c[1][3], a1, b1[2], b1[3]);
        }
        __syncthreads();

        int p0 = t * 64;
        int r = lane >> 2, cq = (lane & 3) * 2;
        #pragma unroll
        for (int i = 0; i < 2; i++) {
            int chA = mb + i * 16 + r;
            size_t gA = (size_t)chA * NPIX + p0;
            size_t gB = gA + (size_t)8 * NPIX;
            #pragma unroll
            for (int j = 0; j < 4; j++) {
                int n = nb + j * 8 + cq;
                float v0 = c[i][j][0], v1 = c[i][j][1], v2 = c[i][j][2], v3 = c[i][j][3];
                st1[i * 2]     += v0 + v1; st2[i * 2]     += v0 * v0 + v1 * v1;
                st1[i * 2 + 1] += v2 + v3; st2[i * 2 + 1] += v2 * v2 + v3 * v3;
                __half2 hh; hh.x = __float2half_rn(v0); hh.y = __float2half_rn(v1);
                *(__half2*)(g_Hh + gA + n) = hh;
                hh.x = __float2half_rn(v2); hh.y = __float2half_rn(v3);
                *(__half2*)(g_Hh + gB + n) = hh;
            }
        }
        buf ^= 1;
    }

    #pragma unroll
    for (int s = 0; s < 4; s++) {
        #pragma unroll
        for (int d = 1; d < 4; d <<= 1) {
            st1[s] += __shfl_xor_sync(0xffffffffu, st1[s], d);
            st2[s] += __shfl_xor_sync(0xffffffffu, st2[s], d);
        }
    }
    if ((lane & 3) == 0) {
        int r = lane >> 2;
        int col = cta * 2 + wc;
        #pragma unroll
        for (int s = 0; s < 4; s++) {
            int ch = wr * 32 + (s >> 1) * 16 + r + (s & 1) * 8;
            g_hpart[((size_t)ch * 296 + col) * 2 + 0] = st1[s];
            g_hpart[((size_t)ch * 296 + col) * 2 + 1] = st2[s];
        }
    }
}

// ---- reduce H stats -> a3, d3 ----
__global__ void k_reduceH(const float* __restrict__ g_mbn, const float* __restrict__ be_mbn) {
    int c = blockIdx.x, t = threadIdx.x;
    double s = 0.0, ss = 0.0;
    for (int i = t; i < 296; i += 128) {
        s  += (double)g_hpart[((size_t)c * 296 + i) * 2 + 0];
        ss += (double)g_hpart[((size_t)c * 296 + i) * 2 + 1];
    }
    __shared__ double sh[128], shh[128];
    sh[t] = s; shh[t] = ss; __syncthreads();
    for (int o = 64; o; o >>= 1) {
        if (t < o) { sh[t] += sh[t + o]; shh[t] += shh[t + o]; }
        __syncthreads();
    }
    if (t == 0) {
        double mu = sh[0] / (double)NPIX;
        double var = shh[0] / (double)NPIX - mu * mu;
        float a = g_mbn[c] / sqrtf((float)var + 1e-5f);
        g_a3[c] = a;
        g_d3[c] = be_mbn[c] - a * (float)mu;
    }
}

// ---- out = a2*yh + b2n + gelu(a3*Hh + d3) ----
__global__ void k_out(float* __restrict__ out) {
    size_t i = ((size_t)blockIdx.x * 256 + threadIdx.x) * 4;
    int c = (int)((i >> 12) & 127);
    size_t b = i >> 19;
    size_t p = b * HW + (i & 4095);
    __half2 yh0 = *(const __half2*)(g_yh + (size_t)c * NPIX + p);
    __half2 yh1 = *(const __half2*)(g_yh + (size_t)c * NPIX + p + 2);
    __half2 hh0 = *(const __half2*)(g_Hh + (size_t)c * NPIX + p);
    __half2 hh1 = *(const __half2*)(g_Hh + (size_t)c * NPIX + p + 2);
    float a2 = g_a[c], bn = g_b2n[c], a3 = g_a3[c], d3 = g_d3[c];
    float4 o;
    o.x = fmaf(a2, __half2float(yh0.x), bn) + gelu(fmaf(a3, __half2float(hh0.x), d3));
    o.y = fmaf(a2, __half2float(yh0.y), bn) + gelu(fmaf(a3, __half2float(hh0.y), d3));
    o.z = fmaf(a2, __half2float(yh1.x), bn) + gelu(fmaf(a3, __half2float(hh1.x), d3));
    o.w = fmaf(a2, __half2float(yh1.y), bn) + gelu(fmaf(a3, __half2float(hh1.y), d3));
    *(float4*)(out + i) = o;
}

extern "C" void kernel_launch(void* const* d_in, const int* in_sizes, int n_in,
                              void* d_out, int out_size) {
    const float* x      = (const float*)d_in[0];
    const float* w_diff = (const float*)d_in[1];
    const float* gbn    = (const float*)d_in[3];
    const float* w_in   = (const float*)d_in[5];
    const float* g_ibn  = (const float*)d_in[7];
    const float* be_ibn = (const float*)d_in[8];
    const float* w_mr   = (const float*)d_in[9];
    const float* g_mbn  = (const float*)d_in[11];
    const float* be_mbn = (const float*)d_in[12];
    float* out = (float*)d_out;

    cudaFuncSetAttribute(k_gemmY, cudaFuncAttributeMaxDynamicSharedMemorySize, SM_Y);
    cudaFuncSetAttribute(k_gemmH, cudaFuncAttributeMaxDynamicSharedMemorySize, SM_H);

    k_fmax<<<4096, 256>>>(x);
    k_gemmY<<<dim3(NCTA, 2), 256, SM_Y>>>(w_in, w_diff);
    k_reduceY<<<256, 128>>>(g_ibn, be_ibn, gbn);
    k_gemmH<<<NCTA, 256, SM_H>>>(w_mr);
    k_reduceH<<<128, 128>>>(g_mbn, be_mbn);
    k_out<<<16384, 256>>>(out);
}

// round 15
// speedup vs baseline: 1.4987x; 1.0108x over previous
#include <cuda_runtime.h>
#include <cuda_fp16.h>
#include <stdint.h>
#include <math.h>

#define HW    4096
#define NPIX  131072
#define NCH   128
#define NT    2048           // 64-pixel tiles
#define NCTA  148

__device__ __half g_xh[(size_t)NCH * NPIX];     // x as fp16
__device__ __half g_fh[(size_t)NCH * NPIX];     // fmax as fp16
__device__ __half g_yh[(size_t)256 * NPIX];     // Y as fp16 (all 256 ch)
__device__ __half g_Hh[(size_t)128 * NPIX];     // H as fp16
__device__ float g_ypart[256 * 296 * 2];
__device__ float g_hpart[128 * 296 * 2];
__device__ float g_a[256];
__device__ float g_b2n[128];
__device__ float g_a3[128];
__device__ float g_d3[128];

__device__ __forceinline__ uint32_t smem_u32(const void* p) {
    uint32_t a;
    asm("{ .reg .u64 t; cvta.to.shared.u64 t, %1; cvt.u32.u64 %0, t; }" : "=r"(a) : "l"(p));
    return a;
}
#define LDSM4(r, addr) \
    asm volatile("ldmatrix.sync.aligned.m8n8.x4.shared.b16 {%0,%1,%2,%3}, [%4];" \
        : "=r"((r)[0]), "=r"((r)[1]), "=r"((r)[2]), "=r"((r)[3]) : "r"(addr))
#define LDSM4T(r, addr) \
    asm volatile("ldmatrix.sync.aligned.m8n8.x4.trans.shared.b16 {%0,%1,%2,%3}, [%4];" \
        : "=r"((r)[0]), "=r"((r)[1]), "=r"((r)[2]), "=r"((r)[3]) : "r"(addr))
#define MMA(c, a, b0v, b1v) \
    asm volatile("mma.sync.aligned.m16n8k16.row.col.f32.f16.f16.f32 " \
        "{%0,%1,%2,%3},{%4,%5,%6,%7},{%8,%9},{%0,%1,%2,%3};" \
        : "+f"((c)[0]), "+f"((c)[1]), "+f"((c)[2]), "+f"((c)[3]) \
        : "r"((a)[0]), "r"((a)[1]), "r"((a)[2]), "r"((a)[3]), "r"(b0v), "r"(b1v))
#define CPA16(s, g) asm volatile("cp.async.cg.shared.global [%0], [%1], 16;" :: "r"(s), "l"(g))
#define CPC()       asm volatile("cp.async.commit_group;" ::: "memory")
#define CPW1()      asm volatile("cp.async.wait_group 1;" ::: "memory")

__device__ __forceinline__ float gelu(float v) { return 0.5f * v * (1.0f + erff(v * 0.70710678f)); }

// ---- K1: fmax; write x and fmax as fp16 ----
__global__ void k_fmax(const float* __restrict__ x) {
    __shared__ float sm[4096];
    size_t o = (size_t)blockIdx.x * HW;
    for (int i = threadIdx.x; i < 4096; i += 256) sm[i] = x[o + i];
    __syncthreads();
    for (int i = threadIdx.x; i < 4096; i += 256) {
        int h = i >> 6, w = i & 63;
        float v = sm[i], m = v;
        #pragma unroll
        for (int s = 2; s <= 32; s <<= 1) {
            m = fminf(m, sm[(h << 6) | ((w + s) & 63)]);
            m = fminf(m, sm[(h << 6) | ((w - s) & 63)]);
            m = fminf(m, sm[(((h + s) & 63) << 6) | w]);
            m = fminf(m, sm[(((h - s) & 63) << 6) | w]);
        }
        g_xh[o + i] = __float2half_rn(v);
        g_fh[o + i] = __float2half_rn(v - m);
    }
}

// ============ GEMM-Y: Y[128ch][64px] = Wh[128x128] * Xh, single pass =========
// SMEM: Ah[128][136] @0 (34816 B), B double buf [128][72] @34816 + b*18432.
#define Y_AS   136
#define Y_BS   72
#define Y_B0   34816u
#define Y_BSZ  18432u
#define SM_Y   71680

__global__ __launch_bounds__(256, 2) void k_gemmY(const float* __restrict__ w_in,
                                                  const float* __restrict__ w_diff) {
    extern __shared__ __align__(16) char smem[];
    const uint32_t sb = smem_u32(smem);
    const int tid = threadIdx.x;
    const int lane = tid & 31, wid = tid >> 5;
    const int wr = wid >> 1, wc = wid & 1;          // 4x2 warp grid
    const int cta = blockIdx.x, ot = blockIdx.y;
    const float* W = ot ? w_diff : w_in;
    const __half* S = ot ? g_fh : g_xh;

    for (int idx = tid; idx < 128 * 128; idx += 256) {
        int m = idx >> 7, k = idx & 127;
        *(__half*)(smem + (m * Y_AS + k) * 2) = __float2half_rn(W[idx]);
    }
    __syncthreads();

    const int la = lane & 15, lb = lane >> 4;
    const int mb = wr * 32, nb = wc * 32;
    const uint32_t aBase = sb + (uint32_t)((mb + la) * Y_AS * 2 + lb * 16);
    const uint32_t bBase = sb + Y_B0 + (uint32_t)(la * Y_BS * 2 + (nb + lb * 8) * 2);

    float st1[4] = {0.f, 0.f, 0.f, 0.f}, st2[4] = {0.f, 0.f, 0.f, 0.f};
    int buf = 0;

    {   // prefetch first tile -> buf0
        int p0 = cta * 64;
        size_t base = (size_t)(p0 >> 12) * 128 * HW + (p0 & 4095);
        #pragma unroll
        for (int rq = 0; rq < 4; rq++) {
            int q = tid + rq * 256;
            int k = q >> 3, c8 = q & 7;
            CPA16(sb + Y_B0 + (uint32_t)(k * Y_BS * 2 + c8 * 16),
                  S + base + (size_t)k * HW + c8 * 8);
        }
        CPC();
    }

    for (int t = cta; t < NT; t += NCTA) {
        int tn = t + NCTA;
        if (tn < NT) {
            int p0n = tn * 64;
            size_t base = (size_t)(p0n >> 12) * 128 * HW + (p0n & 4095);
            uint32_t bo = Y_B0 + (uint32_t)(buf ^ 1) * Y_BSZ;
            #pragma unroll
            for (int rq = 0; rq < 4; rq++) {
                int q = tid + rq * 256;
                int k = q >> 3, c8 = q & 7;
                CPA16(sb + bo + (uint32_t)(k * Y_BS * 2 + c8 * 16),
                      S + base + (size_t)k * HW + c8 * 8);
            }
        }
        CPC(); CPW1();
        __syncthreads();

        float c[2][4][4];
        #pragma unroll
        for (int i = 0; i < 2; i++)
            #pragma unroll
            for (int j = 0; j < 4; j++)
                #pragma unroll
                for (int q = 0; q < 4; q++) c[i][j][q] = 0.f;

        uint32_t bA = bBase + (uint32_t)buf * Y_BSZ;
        #pragma unroll
        for (int ks = 0; ks < 8; ks++) {
            uint32_t a0[4], a1[4], b0[4], b1[4];
            LDSM4(a0, aBase + ks * 32);
            LDSM4(a1, aBase + ks * 32 + 16 * Y_AS * 2);
            LDSM4T(b0, bA + ks * (16 * Y_BS * 2));
            LDSM4T(b1, bA + ks * (16 * Y_BS * 2) + 32);
            MMA(c[0][0], a0, b0[0], b0[1]);
            MMA(c[0][1], a0, b0[2], b0[3]);
            MMA(c[0][2], a0, b1[0], b1[1]);
            MMA(c[0][3], a0, b1[2], b1[3]);
            MMA(c[1][0], a1, b0[0], b0[1]);
            MMA(c[1][1], a1, b0[2], b0[3]);
            MMA(c[1][2], a1, b1[0], b1[1]);
            MMA(c[1][3], a1, b1[2], b1[3]);
        }
        __syncthreads();    // all reads of buf done before refill next iter

        int p0 = t * 64;
        int r = lane >> 2, cq = (lane & 3) * 2;
        #pragma unroll
        for (int i = 0; i < 2; i++) {
            int chA = ot * 128 + mb + i * 16 + r;
            size_t gA = (size_t)chA * NPIX + p0;
            size_t gB = gA + (size_t)8 * NPIX;
            #pragma unroll
            for (int j = 0; j < 4; j++) {
                int n = nb + j * 8 + cq;
                float v0 = c[i][j][0], v1 = c[i][j][1], v2 = c[i][j][2], v3 = c[i][j][3];
                st1[i * 2]     += v0 + v1; st2[i * 2]     += v0 * v0 + v1 * v1;
                st1[i * 2 + 1] += v2 + v3; st2[i * 2 + 1] += v2 * v2 + v3 * v3;
                __half2 hh; hh.x = __float2half_rn(v0); hh.y = __float2half_rn(v1);
                *(__half2*)(g_yh + gA + n) = hh;
                hh.x = __float2half_rn(v2); hh.y = __float2half_rn(v3);
                *(__half2*)(g_yh + gB + n) = hh;
            }
        }
        buf ^= 1;
    }

    #pragma unroll
    for (int s = 0; s < 4; s++) {
        #pragma unroll
        for (int d = 1; d < 4; d <<= 1) {
            st1[s] += __shfl_xor_sync(0xffffffffu, st1[s], d);
            st2[s] += __shfl_xor_sync(0xffffffffu, st2[s], d);
        }
    }
    if ((lane & 3) == 0) {
        int r = lane >> 2;
        int col = cta * 2 + wc;
        #pragma unroll
        for (int s = 0; s < 4; s++) {
            int ch = ot * 128 + wr * 32 + (s >> 1) * 16 + r + (s & 1) * 8;
            g_ypart[((size_t)ch * 296 + col) * 2 + 0] = st1[s];
            g_ypart[((size_t)ch * 296 + col) * 2 + 1] = st2[s];
        }
    }
}

// ---- reduce Y stats -> a[256], b2n[128] ----
__global__ void k_reduceY(const float* __restrict__ g_ibn, const float* __restrict__ be_ibn,
                          const float* __restrict__ gbn) {
    int c = blockIdx.x, t = threadIdx.x;
    double s = 0.0, ss = 0.0;
    for (int i = t; i < 296; i += 128) {
        s  += (double)g_ypart[((size_t)c * 296 + i) * 2 + 0];
        ss += (double)g_ypart[((size_t)c * 296 + i) * 2 + 1];
    }
    __shared__ double sh[128], shh[128];
    sh[t] = s; shh[t] = ss; __syncthreads();
    for (int o = 64; o; o >>= 1) {
        if (t < o) { sh[t] += sh[t + o]; shh[t] += shh[t + o]; }
        __syncthreads();
    }
    if (t == 0) {
        double mu = sh[0] / (double)NPIX;
        double var = shh[0] / (double)NPIX - mu * mu;
        float g = (c < 128) ? g_ibn[c] : gbn[c - 128];
        float a = g / sqrtf((float)var + 1e-5f);
        g_a[c] = a;
        if (c < 128) g_b2n[c] = be_ibn[c] - a * (float)mu;
    }
}

// ============ GEMM-H: H[128][64px] = fp16(w_mr*a)[128x256] * Yh ==============
// A fragments live in REGISTERS (loaded once; loop-invariant across tiles).
// Ah[128][264] @0 (67584 B), B double buf [256][72] @67584 + b*36864.
#define H_AS   264
#define H_BS   72
#define H_B0   67584u
#define H_BSZ  36864u
#define SM_H   141312

__global__ __launch_bounds__(256, 1) void k_gemmH(const float* __restrict__ w_mr) {
    extern __shared__ __align__(16) char smem[];
    const uint32_t sb = smem_u32(smem);
    const int tid = threadIdx.x;
    const int lane = tid & 31, wid = tid >> 5;
    const int wr = wid >> 1, wc = wid & 1;
    const int cta = blockIdx.x;

    // fold BN scale into weights inline
    for (int idx = tid; idx < 128 * 256; idx += 256) {
        int m = idx >> 8, k = idx & 255;
        *(__half*)(smem + (m * H_AS + k) * 2) = __float2half_rn(w_mr[idx] * g_a[k]);
    }
    __syncthreads();

    const int la = lane & 15, lb = lane >> 4;
    const int mb = wr * 32, nb = wc * 32;
    const uint32_t aBase = sb + (uint32_t)((mb + la) * H_AS * 2 + lb * 16);
    const uint32_t bBase = sb + H_B0 + (uint32_t)(la * H_BS * 2 + (nb + lb * 8) * 2);

    // load ALL A fragments into registers once (2 mtiles x 16 ksteps x 4 regs)
    uint32_t aR[2][16][4];
    #pragma unroll
    for (int ks = 0; ks < 16; ks++) {
        LDSM4(aR[0][ks], aBase + ks * 32);
        LDSM4(aR[1][ks], aBase + ks * 32 + 16 * H_AS * 2);
    }

    float st1[4] = {0.f, 0.f, 0.f, 0.f}, st2[4] = {0.f, 0.f, 0.f, 0.f};
    int buf = 0;

    {
        int p0 = cta * 64;
        #pragma unroll
        for (int rq = 0; rq < 8; rq++) {
            int q = tid + rq * 256;
            int k = q >> 3, c8 = q & 7;
            CPA16(sb + H_B0 + (uint32_t)(k * H_BS * 2 + c8 * 16),
                  g_yh + (size_t)k * NPIX + p0 + c8 * 8);
        }
        CPC();
    }

    for (int t = cta; t < NT; t += NCTA) {
        int tn = t + NCTA;
        if (tn < NT) {
            int p0n = tn * 64;
            uint32_t bo = H_B0 + (uint32_t)(buf ^ 1) * H_BSZ;
            #pragma unroll
            for (int rq = 0; rq < 8; rq++) {
                int q = tid + rq * 256;
                int k = q >> 3, c8 = q & 7;
                CPA16(sb + bo + (uint32_t)(k * H_BS * 2 + c8 * 16),
                      g_yh + (size_t)k * NPIX + p0n + c8 * 8);
            }
        }
        CPC(); CPW1();
        __syncthreads();

        float c[2][4][4];
        #pragma unroll
        for (int i = 0; i < 2; i++)
            #pragma unroll
            for (int j = 0; j < 4; j++)
                #pragma unroll
                for (int q = 0; q < 4; q++) c[i][j][q] = 0.f;

        uint32_t bA = bBase + (uint32_t)buf * H_BSZ;
        #pragma unroll
        for (int ks = 0; ks < 16; ks++) {
            uint32_t b0[4], b1[4];
            LDSM4T(b0, bA + ks * (16 * H_BS * 2));
            LDSM4T(b1, bA + ks * (16 * H_BS * 2) + 32);
            MMA(c[0][0], aR[0][ks], b0[0], b0[1]);
            MMA(c[0][1], aR[0][ks], b0[2], b0[3]);
            MMA(c[0][2], aR[0][ks], b1[0], b1[1]);
            MMA(c[0][3], aR[0][ks], b1[2], b1[3]);
            MMA(c[1][0], aR[1][ks], b0[0], b0[1]);
            MMA(c[1][1], aR[1][ks], b0[2], b0[3]);
            MMA(c[1][2], aR[1][ks], b1[0], b1[1]);
            MMA(c[1][3], aR[1][ks], b1[2], b1[3]);
        }
        __syncthreads();

        int p0 = t * 64;
        int r = lane >> 2, cq = (lane & 3) * 2;
        #pragma unroll
        for (int i = 0; i < 2; i++) {
            int chA = mb + i * 16 + r;
            size_t gA = (size_t)chA * NPIX + p0;
            size_t gB = gA + (size_t)8 * NPIX;
            #pragma unroll
            for (int j = 0; j < 4; j++) {
                int n = nb + j * 8 + cq;
                float v0 = c[i][j][0], v1 = c[i][j][1], v2 = c[i][j][2], v3 = c[i][j][3];
                st1[i * 2]     += v0 + v1; st2[i * 2]     += v0 * v0 + v1 * v1;
                st1[i * 2 + 1] += v2 + v3; st2[i * 2 + 1] += v2 * v2 + v3 * v3;
                __half2 hh; hh.x = __float2half_rn(v0); hh.y = __float2half_rn(v1);
                *(__half2*)(g_Hh + gA + n) = hh;
                hh.x = __float2half_rn(v2); hh.y = __float2half_rn(v3);
                *(__half2*)(g_Hh + gB + n) = hh;
            }
        }
        buf ^= 1;
    }

    #pragma unroll
    for (int s = 0; s < 4; s++) {
        #pragma unroll
        for (int d = 1; d < 4; d <<= 1) {
            st1[s] += __shfl_xor_sync(0xffffffffu, st1[s], d);
            st2[s] += __shfl_xor_sync(0xffffffffu, st2[s], d);
        }
    }
    if ((lane & 3) == 0) {
        int r = lane >> 2;
        int col = cta * 2 + wc;
        #pragma unroll
        for (int s = 0; s < 4; s++) {
            int ch = wr * 32 + (s >> 1) * 16 + r + (s & 1) * 8;
            g_hpart[((size_t)ch * 296 + col) * 2 + 0] = st1[s];
            g_hpart[((size_t)ch * 296 + col) * 2 + 1] = st2[s];
        }
    }
}

// ---- reduce H stats -> a3, d3 ----
__global__ void k_reduceH(const float* __restrict__ g_mbn, const float* __restrict__ be_mbn) {
    int c = blockIdx.x, t = threadIdx.x;
    double s = 0.0, ss = 0.0;
    for (int i = t; i < 296; i += 128) {
        s  += (double)g_hpart[((size_t)c * 296 + i) * 2 + 0];
        ss += (double)g_hpart[((size_t)c * 296 + i) * 2 + 1];
    }
    __shared__ double sh[128], shh[128];
    sh[t] = s; shh[t] = ss; __syncthreads();
    for (int o = 64; o; o >>= 1) {
        if (t < o) { sh[t] += sh[t + o]; shh[t] += shh[t + o]; }
        __syncthreads();
    }
    if (t == 0) {
        double mu = sh[0] / (double)NPIX;
        double var = shh[0] / (double)NPIX - mu * mu;
        float a = g_mbn[c] / sqrtf((float)var + 1e-5f);
        g_a3[c] = a;
        g_d3[c] = be_mbn[c] - a * (float)mu;
    }
}

// ---- out = a2*yh + b2n + gelu(a3*Hh + d3) ----
__global__ void k_out(float* __restrict__ out) {
    size_t i = ((size_t)blockIdx.x * 256 + threadIdx.x) * 4;
    int c = (int)((i >> 12) & 127);
    size_t b = i >> 19;
    size_t p = b * HW + (i & 4095);
    __half2 yh0 = *(const __half2*)(g_yh + (size_t)c * NPIX + p);
    __half2 yh1 = *(const __half2*)(g_yh + (size_t)c * NPIX + p + 2);
    __half2 hh0 = *(const __half2*)(g_Hh + (size_t)c * NPIX + p);
    __half2 hh1 = *(const __half2*)(g_Hh + (size_t)c * NPIX + p + 2);
    float a2 = g_a[c], bn = g_b2n[c], a3 = g_a3[c], d3 = g_d3[c];
    float4 o;
    o.x = fmaf(a2, __half2float(yh0.x), bn) + gelu(fmaf(a3, __half2float(hh0.x), d3));
    o.y = fmaf(a2, __half2float(yh0.y), bn) + gelu(fmaf(a3, __half2float(hh0.y), d3));
    o.z = fmaf(a2, __half2float(yh1.x), bn) + gelu(fmaf(a3, __half2float(hh1.x), d3));
    o.w = fmaf(a2, __half2float(yh1.y), bn) + gelu(fmaf(a3, __half2float(hh1.y), d3));
    *(float4*)(out + i) = o;
}

extern "C" void kernel_launch(void* const* d_in, const int* in_sizes, int n_in,
                              void* d_out, int out_size) {
    const float* x      = (const float*)d_in[0];
    const float* w_diff = (const float*)d_in[1];
    const float* gbn    = (const float*)d_in[3];
    const float* w_in   = (const float*)d_in[5];
    const float* g_ibn  = (const float*)d_in[7];
    const float* be_ibn = (const float*)d_in[8];
    const float* w_mr   = (const float*)d_in[9];
    const float* g_mbn  = (const float*)d_in[11];
    const float* be_mbn = (const float*)d_in[12];
    float* out = (float*)d_out;

    cudaFuncSetAttribute(k_gemmY, cudaFuncAttributeMaxDynamicSharedMemorySize, SM_Y);
    cudaFuncSetAttribute(k_gemmH, cudaFuncAttributeMaxDynamicSharedMemorySize, SM_H);

    k_fmax<<<4096, 256>>>(x);
    k_gemmY<<<dim3(NCTA, 2), 256, SM_Y>>>(w_in, w_diff);
    k_reduceY<<<256, 128>>>(g_ibn, be_ibn, gbn);
    k_gemmH<<<NCTA, 256, SM_H>>>(w_mr);
    k_reduceH<<<128, 128>>>(g_mbn, be_mbn);
    k_out<<<16384, 256>>>(out);
}

// round 16
// speedup vs baseline: 1.5045x; 1.0039x over previous
#include <cuda_runtime.h>
#include <cuda_fp16.h>
#include <stdint.h>
#include <math.h>

#define HW    4096
#define NPIX  131072
#define NCH   128
#define NT    2048           // 64-pixel tiles (gemmY)
#define NTH   1024           // 128-pixel tiles (gemmH)
#define NCTA  148

__device__ __half g_xh[(size_t)NCH * NPIX];     // x as fp16
__device__ __half g_fh[(size_t)NCH * NPIX];     // fmax as fp16
__device__ __half g_yh[(size_t)256 * NPIX];     // Y as fp16 (all 256 ch)
__device__ __half g_Hh[(size_t)128 * NPIX];     // H as fp16
__device__ float g_ypart[256 * 296 * 2];
__device__ float g_hpart[128 * 296 * 2];
__device__ float g_a[256];
__device__ float g_b2n[128];
__device__ float g_a3[128];
__device__ float g_d3[128];

__device__ __forceinline__ uint32_t smem_u32(const void* p) {
    uint32_t a;
    asm("{ .reg .u64 t; cvta.to.shared.u64 t, %1; cvt.u32.u64 %0, t; }" : "=r"(a) : "l"(p));
    return a;
}
#define LDSM4(r, addr) \
    asm volatile("ldmatrix.sync.aligned.m8n8.x4.shared.b16 {%0,%1,%2,%3}, [%4];" \
        : "=r"((r)[0]), "=r"((r)[1]), "=r"((r)[2]), "=r"((r)[3]) : "r"(addr))
#define LDSM4T(r, addr) \
    asm volatile("ldmatrix.sync.aligned.m8n8.x4.trans.shared.b16 {%0,%1,%2,%3}, [%4];" \
        : "=r"((r)[0]), "=r"((r)[1]), "=r"((r)[2]), "=r"((r)[3]) : "r"(addr))
#define MMA(c, a, b0v, b1v) \
    asm volatile("mma.sync.aligned.m16n8k16.row.col.f32.f16.f16.f32 " \
        "{%0,%1,%2,%3},{%4,%5,%6,%7},{%8,%9},{%0,%1,%2,%3};" \
        : "+f"((c)[0]), "+f"((c)[1]), "+f"((c)[2]), "+f"((c)[3]) \
        : "r"((a)[0]), "r"((a)[1]), "r"((a)[2]), "r"((a)[3]), "r"(b0v), "r"(b1v))
#define CPA16(s, g) asm volatile("cp.async.cg.shared.global [%0], [%1], 16;" :: "r"(s), "l"(g))
#define CPC()       asm volatile("cp.async.commit_group;" ::: "memory")
#define CPW1()      asm volatile("cp.async.wait_group 1;" ::: "memory")

__device__ __forceinline__ float gelu(float v) { return 0.5f * v * (1.0f + erff(v * 0.70710678f)); }

// ---- K1: fmax; write x and fmax as fp16 ----
__global__ void k_fmax(const float* __restrict__ x) {
    __shared__ float sm[4096];
    size_t o = (size_t)blockIdx.x * HW;
    for (int i = threadIdx.x; i < 4096; i += 256) sm[i] = x[o + i];
    __syncthreads();
    for (int i = threadIdx.x; i < 4096; i += 256) {
        int h = i >> 6, w = i & 63;
        float v = sm[i], m = v;
        #pragma unroll
        for (int s = 2; s <= 32; s <<= 1) {
            m = fminf(m, sm[(h << 6) | ((w + s) & 63)]);
            m = fminf(m, sm[(h << 6) | ((w - s) & 63)]);
            m = fminf(m, sm[(((h + s) & 63) << 6) | w]);
            m = fminf(m, sm[(((h - s) & 63) << 6) | w]);
        }
        g_xh[o + i] = __float2half_rn(v);
        g_fh[o + i] = __float2half_rn(v - m);
    }
}

// ============ GEMM-Y: Y[128ch][64px] = Wh[128x128] * Xh (unchanged) ==========
#define Y_AS   136
#define Y_BS   72
#define Y_B0   34816u
#define Y_BSZ  18432u
#define SM_Y   71680

__global__ __launch_bounds__(256, 2) void k_gemmY(const float* __restrict__ w_in,
                                                  const float* __restrict__ w_diff) {
    extern __shared__ __align__(16) char smem[];
    const uint32_t sb = smem_u32(smem);
    const int tid = threadIdx.x;
    const int lane = tid & 31, wid = tid >> 5;
    const int wr = wid >> 1, wc = wid & 1;          // 4x2 warp grid
    const int cta = blockIdx.x, ot = blockIdx.y;
    const float* W = ot ? w_diff : w_in;
    const __half* S = ot ? g_fh : g_xh;

    for (int idx = tid; idx < 128 * 128; idx += 256) {
        int m = idx >> 7, k = idx & 127;
        *(__half*)(smem + (m * Y_AS + k) * 2) = __float2half_rn(W[idx]);
    }
    __syncthreads();

    const int la = lane & 15, lb = lane >> 4;
    const int mb = wr * 32, nb = wc * 32;
    const uint32_t aBase = sb + (uint32_t)((mb + la) * Y_AS * 2 + lb * 16);
    const uint32_t bBase = sb + Y_B0 + (uint32_t)(la * Y_BS * 2 + (nb + lb * 8) * 2);

    float st1[4] = {0.f, 0.f, 0.f, 0.f}, st2[4] = {0.f, 0.f, 0.f, 0.f};
    int buf = 0;

    {   // prefetch first tile -> buf0
        int p0 = cta * 64;
        size_t base = (size_t)(p0 >> 12) * 128 * HW + (p0 & 4095);
        #pragma unroll
        for (int rq = 0; rq < 4; rq++) {
            int q = tid + rq * 256;
            int k = q >> 3, c8 = q & 7;
            CPA16(sb + Y_B0 + (uint32_t)(k * Y_BS * 2 + c8 * 16),
                  S + base + (size_t)k * HW + c8 * 8);
        }
        CPC();
    }

    for (int t = cta; t < NT; t += NCTA) {
        int tn = t + NCTA;
        if (tn < NT) {
            int p0n = tn * 64;
            size_t base = (size_t)(p0n >> 12) * 128 * HW + (p0n & 4095);
            uint32_t bo = Y_B0 + (uint32_t)(buf ^ 1) * Y_BSZ;
            #pragma unroll
            for (int rq = 0; rq < 4; rq++) {
                int q = tid + rq * 256;
                int k = q >> 3, c8 = q & 7;
                CPA16(sb + bo + (uint32_t)(k * Y_BS * 2 + c8 * 16),
                      S + base + (size_t)k * HW + c8 * 8);
            }
        }
        CPC(); CPW1();
        __syncthreads();

        float c[2][4][4];
        #pragma unroll
        for (int i = 0; i < 2; i++)
            #pragma unroll
            for (int j = 0; j < 4; j++)
                #pragma unroll
                for (int q = 0; q < 4; q++) c[i][j][q] = 0.f;

        uint32_t bA = bBase + (uint32_t)buf * Y_BSZ;
        #pragma unroll
        for (int ks = 0; ks < 8; ks++) {
            uint32_t a0[4], a1[4], b0[4], b1[4];
            LDSM4(a0, aBase + ks * 32);
            LDSM4(a1, aBase + ks * 32 + 16 * Y_AS * 2);
            LDSM4T(b0, bA + ks * (16 * Y_BS * 2));
            LDSM4T(b1, bA + ks * (16 * Y_BS * 2) + 32);
            MMA(c[0][0], a0, b0[0], b0[1]);
            MMA(c[0][1], a0, b0[2], b0[3]);
            MMA(c[0][2], a0, b1[0], b1[1]);
            MMA(c[0][3], a0, b1[2], b1[3]);
            MMA(c[1][0], a1, b0[0], b0[1]);
            MMA(c[1][1], a1, b0[2], b0[3]);
            MMA(c[1][2], a1, b1[0], b1[1]);
            MMA(c[1][3], a1, b1[2], b1[3]);
        }
        __syncthreads();

        int p0 = t * 64;
        int r = lane >> 2, cq = (lane & 3) * 2;
        #pragma unroll
        for (int i = 0; i < 2; i++) {
            int chA = ot * 128 + mb + i * 16 + r;
            size_t gA = (size_t)chA * NPIX + p0;
            size_t gB = gA + (size_t)8 * NPIX;
            #pragma unroll
            for (int j = 0; j < 4; j++) {
                int n = nb + j * 8 + cq;
                float v0 = c[i][j][0], v1 = c[i][j][1], v2 = c[i][j][2], v3 = c[i][j][3];
                st1[i * 2]     += v0 + v1; st2[i * 2]     += v0 * v0 + v1 * v1;
                st1[i * 2 + 1] += v2 + v3; st2[i * 2 + 1] += v2 * v2 + v3 * v3;
                __half2 hh; hh.x = __float2half_rn(v0); hh.y = __float2half_rn(v1);
                *(__half2*)(g_yh + gA + n) = hh;
                hh.x = __float2half_rn(v2); hh.y = __float2half_rn(v3);
                *(__half2*)(g_yh + gB + n) = hh;
            }
        }
        buf ^= 1;
    }

    #pragma unroll
    for (int s = 0; s < 4; s++) {
        #pragma unroll
        for (int d = 1; d < 4; d <<= 1) {
            st1[s] += __shfl_xor_sync(0xffffffffu, st1[s], d);
            st2[s] += __shfl_xor_sync(0xffffffffu, st2[s], d);
        }
    }
    if ((lane & 3) == 0) {
        int r = lane >> 2;
        int col = cta * 2 + wc;
        #pragma unroll
        for (int s = 0; s < 4; s++) {
            int ch = ot * 128 + wr * 32 + (s >> 1) * 16 + r + (s & 1) * 8;
            g_ypart[((size_t)ch * 296 + col) * 2 + 0] = st1[s];
            g_ypart[((size_t)ch * 296 + col) * 2 + 1] = st2[s];
        }
    }
}

// ---- reduce Y stats -> a[256], b2n[128] ----
__global__ void k_reduceY(const float* __restrict__ g_ibn, const float* __restrict__ be_ibn,
                          const float* __restrict__ gbn) {
    int c = blockIdx.x, t = threadIdx.x;
    double s = 0.0, ss = 0.0;
    for (int i = t; i < 296; i += 128) {
        s  += (double)g_ypart[((size_t)c * 296 + i) * 2 + 0];
        ss += (double)g_ypart[((size_t)c * 296 + i) * 2 + 1];
    }
    __shared__ double sh[128], shh[128];
    sh[t] = s; shh[t] = ss; __syncthreads();
    for (int o = 64; o; o >>= 1) {
        if (t < o) { sh[t] += sh[t + o]; shh[t] += shh[t + o]; }
        __syncthreads();
    }
    if (t == 0) {
        double mu = sh[0] / (double)NPIX;
        double var = shh[0] / (double)NPIX - mu * mu;
        float g = (c < 128) ? g_ibn[c] : gbn[c - 128];
        float a = g / sqrtf((float)var + 1e-5f);
        g_a[c] = a;
        if (c < 128) g_b2n[c] = be_ibn[c] - a * (float)mu;
    }
}

// ============ GEMM-H: H[128ch][128px tile] = fp16(w_mr*a)[128x256] * Yh ======
// N=128 tile: Ah[128][264] @0 (67584 B), B double buf [256][136] @67584 + b*69632.
#define H_AS   264
#define H_BS   136
#define H_B0   67584u
#define H_BSZ  69632u
#define SM_H   206848

__global__ __launch_bounds__(256, 1) void k_gemmH(const float* __restrict__ w_mr) {
    extern __shared__ __align__(16) char smem[];
    const uint32_t sb = smem_u32(smem);
    const int tid = threadIdx.x;
    const int lane = tid & 31, wid = tid >> 5;
    const int wr = wid >> 1, wc = wid & 1;          // 4x2 warps: M32 x N64 each
    const int cta = blockIdx.x;

    // fold BN scale into weights inline
    for (int idx = tid; idx < 128 * 256; idx += 256) {
        int m = idx >> 8, k = idx & 255;
        *(__half*)(smem + (m * H_AS + k) * 2) = __float2half_rn(w_mr[idx] * g_a[k]);
    }
    __syncthreads();

    const int la = lane & 15, lb = lane >> 4;
    const int mb = wr * 32, nb = wc * 64;
    const uint32_t aBase = sb + (uint32_t)((mb + la) * H_AS * 2 + lb * 16);
    const uint32_t bBase = sb + H_B0 + (uint32_t)(la * H_BS * 2 + (nb + lb * 8) * 2);

    float st1[4] = {0.f, 0.f, 0.f, 0.f}, st2[4] = {0.f, 0.f, 0.f, 0.f};
    int buf = 0;

    {   // prefetch first tile: 256 k-rows x 128 px fp16 = 64 KB -> 4096 chunks
        int p0 = cta * 128;
        #pragma unroll
        for (int rq = 0; rq < 16; rq++) {
            int q = tid + rq * 256;
            int k = q >> 4, c16 = q & 15;
            CPA16(sb + H_B0 + (uint32_t)(k * H_BS * 2 + c16 * 16),
                  g_yh + (size_t)k * NPIX + p0 + c16 * 8);
        }
        CPC();
    }

    for (int t = cta; t < NTH; t += NCTA) {
        int tn = t + NCTA;
        if (tn < NTH) {
            int p0n = tn * 128;
            uint32_t bo = H_B0 + (uint32_t)(buf ^ 1) * H_BSZ;
            #pragma unroll
            for (int rq = 0; rq < 16; rq++) {
                int q = tid + rq * 256;
                int k = q >> 4, c16 = q & 15;
                CPA16(sb + bo + (uint32_t)(k * H_BS * 2 + c16 * 16),
                      g_yh + (size_t)k * NPIX + p0n + c16 * 8);
            }
        }
        CPC(); CPW1();
        __syncthreads();

        float c[2][8][4];
        #pragma unroll
        for (int i = 0; i < 2; i++)
            #pragma unroll
            for (int j = 0; j < 8; j++)
                #pragma unroll
                for (int q = 0; q < 4; q++) c[i][j][q] = 0.f;

        uint32_t bA = bBase + (uint32_t)buf * H_BSZ;
        #pragma unroll
        for (int ks = 0; ks < 16; ks++) {
            uint32_t a0[4], a1[4], bF[4][4];
            LDSM4(a0, aBase + ks * 32);
            LDSM4(a1, aBase + ks * 32 + 16 * H_AS * 2);
            #pragma unroll
            for (int f = 0; f < 4; f++)
                LDSM4T(bF[f], bA + ks * (16 * H_BS * 2) + f * 32);
            #pragma unroll
            for (int j = 0; j < 8; j++) {
                MMA(c[0][j], a0, bF[j >> 1][(j & 1) * 2], bF[j >> 1][(j & 1) * 2 + 1]);
                MMA(c[1][j], a1, bF[j >> 1][(j & 1) * 2], bF[j >> 1][(j & 1) * 2 + 1]);
            }
        }
        __syncthreads();

        int p0 = t * 128;
        int r = lane >> 2, cq = (lane & 3) * 2;
        #pragma unroll
        for (int i = 0; i < 2; i++) {
            int chA = mb + i * 16 + r;
            size_t gA = (size_t)chA * NPIX + p0;
            size_t gB = gA + (size_t)8 * NPIX;
            #pragma unroll
            for (int j = 0; j < 8; j++) {
                int n = nb + j * 8 + cq;
                float v0 = c[i][j][0], v1 = c[i][j][1], v2 = c[i][j][2], v3 = c[i][j][3];
                st1[i * 2]     += v0 + v1; st2[i * 2]     += v0 * v0 + v1 * v1;
                st1[i * 2 + 1] += v2 + v3; st2[i * 2 + 1] += v2 * v2 + v3 * v3;
                __half2 hh; hh.x = __float2half_rn(v0); hh.y = __float2half_rn(v1);
                *(__half2*)(g_Hh + gA + n) = hh;
                hh.x = __float2half_rn(v2); hh.y = __float2half_rn(v3);
                *(__half2*)(g_Hh + gB + n) = hh;
            }
        }
        buf ^= 1;
    }

    #pragma unroll
    for (int s = 0; s < 4; s++) {
        #pragma unroll
        for (int d = 1; d < 4; d <<= 1) {
            st1[s] += __shfl_xor_sync(0xffffffffu, st1[s], d);
            st2[s] += __shfl_xor_sync(0xffffffffu, st2[s], d);
        }
    }
    if ((lane & 3) == 0) {
        int r = lane >> 2;
        int col = cta * 2 + wc;
        #pragma unroll
        for (int s = 0; s < 4; s++) {
            int ch = wr * 32 + (s >> 1) * 16 + r + (s & 1) * 8;
            g_hpart[((size_t)ch * 296 + col) * 2 + 0] = st1[s];
            g_hpart[((size_t)ch * 296 + col) * 2 + 1] = st2[s];
        }
    }
}

// ---- reduce H stats -> a3, d3 ----
__global__ void k_reduceH(const float* __restrict__ g_mbn, const float* __restrict__ be_mbn) {
    int c = blockIdx.x, t = threadIdx.x;
    double s = 0.0, ss = 0.0;
    for (int i = t; i < 296; i += 128) {
        s  += (double)g_hpart[((size_t)c * 296 + i) * 2 + 0];
        ss += (double)g_hpart[((size_t)c * 296 + i) * 2 + 1];
    }
    __shared__ double sh[128], shh[128];
    sh[t] = s; shh[t] = ss; __syncthreads();
    for (int o = 64; o; o >>= 1) {
        if (t < o) { sh[t] += sh[t + o]; shh[t] += shh[t + o]; }
        __syncthreads();
    }
    if (t == 0) {
        double mu = sh[0] / (double)NPIX;
        double var = shh[0] / (double)NPIX - mu * mu;
        float a = g_mbn[c] / sqrtf((float)var + 1e-5f);
        g_a3[c] = a;
        g_d3[c] = be_mbn[c] - a * (float)mu;
    }
}

// ---- out = a2*yh + b2n + gelu(a3*Hh + d3) ----
__global__ void k_out(float* __restrict__ out) {
    size_t i = ((size_t)blockIdx.x * 256 + threadIdx.x) * 4;
    int c = (int)((i >> 12) & 127);
    size_t b = i >> 19;
    size_t p = b * HW + (i & 4095);
    __half2 yh0 = *(const __half2*)(g_yh + (size_t)c * NPIX + p);
    __half2 yh1 = *(const __half2*)(g_yh + (size_t)c * NPIX + p + 2);
    __half2 hh0 = *(const __half2*)(g_Hh + (size_t)c * NPIX + p);
    __half2 hh1 = *(const __half2*)(g_Hh + (size_t)c * NPIX + p + 2);
    float a2 = g_a[c], bn = g_b2n[c], a3 = g_a3[c], d3 = g_d3[c];
    float4 o;
    o.x = fmaf(a2, __half2float(yh0.x), bn) + gelu(fmaf(a3, __half2float(hh0.x), d3));
    o.y = fmaf(a2, __half2float(yh0.y), bn) + gelu(fmaf(a3, __half2float(hh0.y), d3));
    o.z = fmaf(a2, __half2float(yh1.x), bn) + gelu(fmaf(a3, __half2float(hh1.x), d3));
    o.w = fmaf(a2, __half2float(yh1.y), bn) + gelu(fmaf(a3, __half2float(hh1.y), d3));
    *(float4*)(out + i) = o;
}

extern "C" void kernel_launch(void* const* d_in, const int* in_sizes, int n_in,
                              void* d_out, int out_size) {
    const float* x      = (const float*)d_in[0];
    const float* w_diff = (const float*)d_in[1];
    const float* gbn    = (const float*)d_in[3];
    const float* w_in   = (const float*)d_in[5];
    const float* g_ibn  = (const float*)d_in[7];
    const float* be_ibn = (const float*)d_in[8];
    const float* w_mr   = (const float*)d_in[9];
    const float* g_mbn  = (const float*)d_in[11];
    const float* be_mbn = (const float*)d_in[12];
    float* out = (float*)d_out;

    cudaFuncSetAttribute(k_gemmY, cudaFuncAttributeMaxDynamicSharedMemorySize, SM_Y);
    cudaFuncSetAttribute(k_gemmH, cudaFuncAttributeMaxDynamicSharedMemorySize, SM_H);

    k_fmax<<<4096, 256>>>(x);
    k_gemmY<<<dim3(NCTA, 2), 256, SM_Y>>>(w_in, w_diff);
    k_reduceY<<<256, 128>>>(g_ibn, be_ibn, gbn);
    k_gemmH<<<NCTA, 256, SM_H>>>(w_mr);
    k_reduceH<<<128, 128>>>(g_mbn, be_mbn);
    k_out<<<16384, 256>>>(out);
}